// round 14
// baseline (speedup 1.0000x reference)
#include <cuda_runtime.h>
#include <cuda_fp16.h>
#include <math.h>
#include <stdint.h>

#define BB 8
#define TT 90
#define HIMG 290
#define WIMG 180
#define PS 10
#define NWP 18
#define NP 522
#define PD 100
#define NV 94
#define KVIS 24
#define LL 2160
#define DD 256
#define NHEAD 8
#define DH 32
#define NLAYERS 6
#define DFF 1024
#define MM (BB*LL)   /* 17280 */
#define LTP 2176     /* LL padded to 68*32 */
#define ASCALE 0.17677669529663687f
#define QSCALE (0.17677669529663687f * 1.4426950408889634f)  /* fold log2e */

// per-layer weight segment offsets (elements), layer stride
#define WOFS_QKV 0
#define WOFS_O   196608
#define WOFS_1   262144
#define WOFS_2   524288
#define WLAYER   786432
#define WTOTAL   (6*WLAYER)

// ---------------- scratch (no cudaMalloc allowed) ----------------
__device__ float g_x[MM*DD];
__device__ float g_y[MM*DD];
__device__ __half g_xh[MM*DD],  g_xl[MM*DD];
__device__ __half g_atth[MM*DD];                   // attention out, single fp16
__device__ __half g_ffh[MM*DFF];                   // FF1 out, single fp16
__device__ __half g_qh[BB*NHEAD*LL*DH];            // Q single fp16 (pre-scaled)
__device__ __half g_kh[BB*NHEAD*LL*DH];            // K single fp16
__device__ __half g_vth[BB*NHEAD*DH*LTP];          // V single fp16, transposed
__device__ __half g_wh[WTOTAL];                    // weights single fp16
__device__ int   g_tokv[MM];

// ---------------- helpers ----------------
__device__ __forceinline__ unsigned sptr(const void* p) {
    return (unsigned)__cvta_generic_to_shared(p);
}
__device__ __forceinline__ void ldsm4(unsigned &r0, unsigned &r1, unsigned &r2, unsigned &r3, unsigned addr) {
    asm volatile("ldmatrix.sync.aligned.m8n8.x4.shared.b16 {%0,%1,%2,%3}, [%4];"
                 : "=r"(r0), "=r"(r1), "=r"(r2), "=r"(r3) : "r"(addr));
}
__device__ __forceinline__ void mma_f16(float* c, const unsigned* a, unsigned b0, unsigned b1) {
    asm volatile("mma.sync.aligned.m16n8k16.row.col.f32.f16.f16.f32 "
                 "{%0,%1,%2,%3}, {%4,%5,%6,%7}, {%8,%9}, {%0,%1,%2,%3};"
                 : "+f"(c[0]), "+f"(c[1]), "+f"(c[2]), "+f"(c[3])
                 : "r"(a[0]), "r"(a[1]), "r"(a[2]), "r"(a[3]), "r"(b0), "r"(b1));
}
// split two f32 into packed fp16 hi and lo words
__device__ __forceinline__ void split2(float x0, float x1, unsigned &h, unsigned &l) {
    __half h0 = __float2half_rn(x0), h1 = __float2half_rn(x1);
    float r0 = x0 - __half2float(h0), r1 = x1 - __half2float(h1);
    __half l0 = __float2half_rn(r0), l1 = __float2half_rn(r1);
    h = (unsigned)__half_as_ushort(h0) | ((unsigned)__half_as_ushort(h1) << 16);
    l = (unsigned)__half_as_ushort(l0) | ((unsigned)__half_as_ushort(l1) << 16);
}
// pack two f32 as fp16 pair (hi only)
__device__ __forceinline__ unsigned packh(float x0, float x1) {
    __half h0 = __float2half_rn(x0), h1 = __float2half_rn(x1);
    return (unsigned)__half_as_ushort(h0) | ((unsigned)__half_as_ushort(h1) << 16);
}
__device__ __forceinline__ void cp16(uint32_t dst, const void* src) {
    asm volatile("cp.async.cg.shared.global [%0], [%1], 16;" :: "r"(dst), "l"(src) : "memory");
}
__device__ __forceinline__ void cp16p(uint32_t dst, const void* src, int pred) {
    int sz = pred ? 16 : 0;
    asm volatile("cp.async.cg.shared.global [%0], [%1], 16, %2;" :: "r"(dst), "l"(src), "r"(sz) : "memory");
}
#define CP_COMMIT() asm volatile("cp.async.commit_group;" ::: "memory")
#define CP_WAIT1()  asm volatile("cp.async.wait_group 1;" ::: "memory")

// ---------------- token list ----------------
__global__ void build_vis_kernel(const void* __restrict__ mask_raw,
                                 const int* __restrict__ valid_idx)
{
    int bt = blockIdx.x*blockDim.x + threadIdx.x;
    if (bt >= BB*TT) return;
    const int*   mi = (const int*)mask_raw;
    const float* mf = (const float*)mask_raw;
    const unsigned char* mb = (const unsigned char*)mask_raw;
    int is_int = 1;
    for (int j = 0; j < NP; j++) { int w = mi[j]; if (w != 0 && w != 1) { is_int = 0; break; } }
    int is_float = 0;
    if (!is_int) {
        is_float = 1;
        for (int j = 0; j < NP; j++) { float w = mf[j]; if (w != 0.0f && w != 1.0f) { is_float = 0; break; } }
    }
    int base = bt*KVIS, cnt = 0;
    for (int v = 0; v < NV; v++) {
        int idx = bt*NP + valid_idx[v];
        int masked;
        if (is_int)        masked = (mi[idx] != 0);
        else if (is_float) masked = (mf[idx] != 0.0f);
        else               masked = (mb[idx] != 0);
        if (!masked) { if (cnt < KVIS) g_tokv[base+cnt] = v; cnt++; }
    }
}

// ---------------- patchify + patch embed + pos encodings ----------------
__global__ void __launch_bounds__(256) embed_kernel(
    const float* __restrict__ img, const int* __restrict__ valid_idx,
    const float* __restrict__ Wpe, const float* __restrict__ bpe,
    const float* __restrict__ spos)
{
    __shared__ float pix[16][PD];
    __shared__ float wsm[DD][27];
    __shared__ int sm_v[16], sm_t[16], sm_off[16];
    int tid = threadIdx.x;
    int m0 = blockIdx.x * 16;
    if (tid < 16) {
        int m = m0 + tid;
        int b = m / LL;
        int l = m - b*LL;
        int t = l / KVIS;
        int v = g_tokv[m];
        int patch = valid_idx[v];
        int hp = patch / NWP, wp = patch - hp*NWP;
        sm_v[tid] = v; sm_t[tid] = t;
        sm_off[tid] = ((b*TT + t)*HIMG + hp*PS)*WIMG + wp*PS;
    }
    __syncthreads();
    for (int j = tid; j < 16*PD; j += 256) {
        int tok = j / PD, pd = j - tok*PD;
        int ph = pd / PS, pw = pd - ph*PS;
        pix[tok][pd] = img[sm_off[tok] + ph*WIMG + pw];
    }
    float acc[16];
    #pragma unroll
    for (int i = 0; i < 16; i++) acc[i] = 0.f;
    for (int k0 = 0; k0 < PD; k0 += 25) {
        __syncthreads();
        for (int j = tid; j < DD*25; j += 256) {
            int dd = j / 25, kk = j - dd*25;
            wsm[dd][kk] = Wpe[dd*PD + k0 + kk];
        }
        __syncthreads();
        #pragma unroll
        for (int kk = 0; kk < 25; kk++) {
            float w = wsm[tid][kk];
            #pragma unroll
            for (int tok = 0; tok < 16; tok++)
                acc[tok] = fmaf(w, pix[tok][k0+kk], acc[tok]);
        }
    }
    int d = tid;
    float freq = expf((float)(d & ~1) * (-9.210340371976184f / 256.f));
    float pb = bpe[d];
    #pragma unroll
    for (int tok = 0; tok < 16; tok++) {
        float val = (float)sm_t[tok] * freq;
        float pe = (d & 1) ? cosf(val) : sinf(val);
        g_x[(m0+tok)*DD + d] = acc[tok] + pb + spos[sm_v[tok]*DD + d] + pe;
    }
}

// ---------------- one-time prep: weights -> single fp16, layer-major -------
__global__ void prep_weights_kernel(const float* __restrict__ Wqkv, const float* __restrict__ Wo,
                                    const float* __restrict__ W1, const float* __restrict__ W2)
{
    int i = blockIdx.x*blockDim.x + threadIdx.x;
    int layer = i / WLAYER;
    int r = i - layer*WLAYER;
    float v;
    if      (r < WOFS_O) v = Wqkv[layer*196608 + r];
    else if (r < WOFS_1) v = Wo[layer*65536 + r - WOFS_O];
    else if (r < WOFS_2) v = W1[layer*262144 + r - WOFS_1];
    else                 v = W2[layer*262144 + r - WOFS_2];
    g_wh[i] = __float2half_rn(v);
}

// ---------------- x fp32 -> hi/lo fp16 (after embed only) ----------------
__global__ void cvt_x_kernel()
{
    int i = blockIdx.x*blockDim.x + threadIdx.x;   // over MM*DD/2
    float2 v = ((const float2*)g_x)[i];
    unsigned h, l; split2(v.x, v.y, h, l);
    ((unsigned*)g_xh)[i] = h;
    ((unsigned*)g_xl)[i] = l;
}

// ---------------- fp16 tensor-core GEMM, 3-stage cp.async ring -------------
// C[m,n] = sum_k A[m,k]*W[n,k] + bias[n].  A aterms-term, W single.
// smem slots per stage: 0=Ah, 1=Wh, 2=Al (optional).
// outmode: 0 fp32 C; 1 fp16 Ch; 2 fused QKV epilogue.
#define GSTR 24
#define GARR (128*GSTR)
#define GSTAGE (3*GARR)
#define GEMM_SMEM (3*GSTAGE*2)

__global__ void __launch_bounds__(256,2) gemm_kernel(
    const __half* __restrict__ Ahg, const __half* __restrict__ Alg,
    const __half* __restrict__ Whg,
    const float* __restrict__ bias,
    float* __restrict__ C, __half* __restrict__ Ch,
    int Ndim, int Kdim, int relu, int outmode, int aterms)
{
    extern __shared__ __align__(16) char smraw[];
    __half* smb = (__half*)smraw;
    uint32_t smb_u = sptr(smraw);
    int tid = threadIdx.x, lane = tid & 31, wid = tid >> 5;
    int wm = wid >> 1, wn = wid & 1;
    int m0 = blockIdx.x*128, n0 = blockIdx.y*128;
    int narr = aterms + 1;   // 2 or 3

    const __half* srcs[3] = {
        Ahg + (size_t)m0*Kdim,
        Whg + (size_t)n0*Kdim,
        (aterms == 2) ? (Alg + (size_t)m0*Kdim) : (Ahg + (size_t)m0*Kdim) };

    float acc[2][8][4];
    #pragma unroll
    for (int i=0;i<2;i++)
        #pragma unroll
        for (int j=0;j<8;j++)
            #pragma unroll
            for (int q=0;q<4;q++) acc[i][j][q]=0.f;

    int arow = wm*32 + (lane & 15);
    int akoff = (lane >> 4) << 3;
    int brow = wn*64 + ((lane >> 4) << 3) + (lane & 7);
    int bkoff = ((lane >> 3) & 1) << 3;

    #define GEMM_ISSUE(s, k0) do { \
        uint32_t base_ = smb_u + (s)*GSTAGE*2; \
        _Pragma("unroll") \
        for (int it_ = 0; it_ < 3; it_++) { \
            if (it_ < narr) { \
                int idx_ = it_*256 + tid; \
                int arr_ = idx_ >> 8, rem_ = idx_ & 255; \
                int row_ = rem_ >> 1, ch_ = rem_ & 1; \
                const void* gp_ = srcs[arr_] + (size_t)row_*Kdim + (k0) + ch_*8; \
                uint32_t dst_ = base_ + (arr_*GARR + row_*GSTR + ch_*8)*2; \
                cp16(dst_, gp_); \
            } \
        } \
    } while(0)

    GEMM_ISSUE(0, 0);  CP_COMMIT();
    GEMM_ISSUE(1, 16); CP_COMMIT();

    int NTK = Kdim >> 4;
    for (int t = 0; t < NTK; t++) {
        CP_WAIT1();
        __syncthreads();
        if (t + 2 < NTK) {
            int s = (t+2) % 3;
            GEMM_ISSUE(s, (t+2)*16);
        }
        CP_COMMIT();

        __half* Ah = smb + (t%3)*GSTAGE;
        __half* Wh = Ah + GARR;
        __half* Al = Wh + GARR;

        unsigned ah0[4], ah1[4];
        ldsm4(ah0[0],ah0[1],ah0[2],ah0[3], sptr(Ah + arow*GSTR + akoff));
        ldsm4(ah1[0],ah1[1],ah1[2],ah1[3], sptr(Ah + (arow+16)*GSTR + akoff));

        unsigned bf[4][4];
        #pragma unroll
        for (int p = 0; p < 4; p++)
            ldsm4(bf[p][0],bf[p][1],bf[p][2],bf[p][3], sptr(Wh + (brow + p*16)*GSTR + bkoff));
        // pass 1: Ah x Wh
        #pragma unroll
        for (int p = 0; p < 4; p++) {
            mma_f16(acc[0][2*p],   ah0, bf[p][0], bf[p][1]);
            mma_f16(acc[0][2*p+1], ah0, bf[p][2], bf[p][3]);
            mma_f16(acc[1][2*p],   ah1, bf[p][0], bf[p][1]);
            mma_f16(acc[1][2*p+1], ah1, bf[p][2], bf[p][3]);
        }
        // pass 2: Al x Wh (only when aterms == 2)
        if (aterms == 2) {
            unsigned al0[4], al1[4];
            ldsm4(al0[0],al0[1],al0[2],al0[3], sptr(Al + arow*GSTR + akoff));
            ldsm4(al1[0],al1[1],al1[2],al1[3], sptr(Al + (arow+16)*GSTR + akoff));
            #pragma unroll
            for (int p = 0; p < 4; p++) {
                mma_f16(acc[0][2*p],   al0, bf[p][0], bf[p][1]);
                mma_f16(acc[0][2*p+1], al0, bf[p][2], bf[p][3]);
                mma_f16(acc[1][2*p],   al1, bf[p][0], bf[p][1]);
                mma_f16(acc[1][2*p+1], al1, bf[p][2], bf[p][3]);
            }
        }
        __syncthreads();
    }

    // epilogue
    int r0 = lane >> 2;
    int c2 = (lane & 3) << 1;
    #pragma unroll
    for (int ma = 0; ma < 2; ma++) {
        #pragma unroll
        for (int na = 0; na < 8; na++) {
            int col = n0 + wn*64 + na*8 + c2;
            float2 bsv = *(const float2*)(bias + col);
            float v0 = acc[ma][na][0] + bsv.x;
            float v1 = acc[ma][na][1] + bsv.y;
            float v2 = acc[ma][na][2] + bsv.x;
            float v3 = acc[ma][na][3] + bsv.y;
            int row = m0 + wm*32 + ma*16 + r0;
            if (outmode == 2) {
                // fused QKV: seg 0=Q(scaled,single), 1=K(single), 2=V^T(single)
                int seg = col >> 8;
                int h = (col >> 5) & 7;
                int dh = col & 31;
                if (seg == 0) { v0 *= QSCALE; v1 *= QSCALE; v2 *= QSCALE; v3 *= QSCALE; }
                #pragma unroll
                for (int half = 0; half < 2; half++) {
                    int rr = row + half*8;
                    float a0 = half ? v2 : v0;
                    float a1 = half ? v3 : v1;
                    int bb = rr / LL;
                    int l = rr - bb*LL;
                    int bh = bb*8 + h;
                    if (seg < 2) {
                        size_t o = ((size_t)bh*LL + l)*16 + (dh >> 1);
                        ((unsigned*)(seg == 0 ? g_qh : g_kh))[o] = packh(a0, a1);
                    } else {
                        size_t o0 = ((size_t)bh*32 + dh)*LTP + l;
                        size_t o1 = ((size_t)bh*32 + dh + 1)*LTP + l;
                        g_vth[o0] = __float2half_rn(a0);
                        g_vth[o1] = __float2half_rn(a1);
                    }
                }
            } else {
                if (relu) {
                    v0 = fmaxf(v0,0.f); v1 = fmaxf(v1,0.f);
                    v2 = fmaxf(v2,0.f); v3 = fmaxf(v3,0.f);
                }
                if (outmode == 1) {
                    size_t o = ((size_t)row*Ndim + col) >> 1;
                    ((unsigned*)Ch)[o] = packh(v0, v1);
                    o = ((size_t)(row+8)*Ndim + col) >> 1;
                    ((unsigned*)Ch)[o] = packh(v2, v3);
                } else {
                    *(float2*)(C + (size_t)row*Ndim + col) = make_float2(v0, v1);
                    *(float2*)(C + (size_t)(row+8)*Ndim + col) = make_float2(v2, v3);
                }
            }
        }
    }
}

// ---------------- flash attention, pure fp16 operands, exp2 softmax --------
// QK 1-term (Qh x Kh), PV 1-term (Ph x Vh). Logits in log2 units.
#define AQ_ELEMS (128*40)
#define AKV_ELEMS 4864
#define ATT_SMEM ((AQ_ELEMS + 3*AKV_ELEMS)*2)

__global__ void __launch_bounds__(256,2) attn_kernel(__half* __restrict__ outh)
{
    extern __shared__ __align__(16) char smraw[];
    __half* smb = (__half*)smraw;
    uint32_t smb_u = sptr(smraw);
    __half* Qhs = smb;                 // [128][40]

    int tid = threadIdx.x, lane = tid & 31, wid = tid >> 5;
    int q0 = blockIdx.x * 128;
    int bh = blockIdx.y;
    int b = bh >> 3, h = bh & 7;

    #define ATT_ISSUE(s, k0t) do { \
        uint32_t sb_ = smb_u + (AQ_ELEMS + (s)*AKV_ELEMS)*2; \
        _Pragma("unroll") \
        for (int it_ = 0; it_ < 2; it_++) { \
            int idx_ = it_*256 + tid; \
            if (idx_ < 256) { \
                int r_ = idx_ >> 2, c_ = idx_ & 3; \
                int krow_ = (k0t) + r_; \
                int pred_ = (krow_ < LL); \
                int kc_ = pred_ ? krow_ : 0; \
                const __half* src_ = g_kh + ((size_t)bh*LL + kc_)*32 + c_*8; \
                uint32_t dst_ = sb_ + (r_*40 + c_*8)*2; \
                cp16p(dst_, src_, pred_); \
            } else { \
                int j_ = idx_ - 256; \
                int dd_ = j_ >> 3, c_ = j_ & 7; \
                const __half* src_ = g_vth + ((size_t)bh*32 + dd_)*LTP + (k0t) + c_*8; \
                uint32_t dst_ = sb_ + (2560 + dd_*72 + c_*8)*2; \
                cp16(dst_, src_); \
            } \
        } \
    } while(0)

    // ---- Q copy via cp.async ----
    #pragma unroll
    for (int it = 0; it < 2; it++) {
        int idx = it*256 + tid;
        int r = idx >> 2, c = idx & 3;
        int qrow = q0 + r;
        int pred = (qrow < LL);
        int qc = pred ? qrow : 0;
        const __half* src = g_qh + ((size_t)bh*LL + qc)*32 + c*8;
        uint32_t dst = smb_u + (r*40 + c*8)*2;
        cp16p(dst, src, pred);
    }
    ATT_ISSUE(0, 0);  CP_COMMIT();
    ATT_ISSUE(1, 64); CP_COMMIT();

    int arow = wid*16 + (lane & 15);
    int akoff = (lane >> 4) << 3;
    int brow = ((lane >> 4) << 3) + (lane & 7);
    int bkoff = ((lane >> 3) & 1) << 3;
    int c2 = (lane & 3) << 1;

    float sO[4][4];
    #pragma unroll
    for (int i=0;i<4;i++)
        #pragma unroll
        for (int j=0;j<4;j++) sO[i][j]=0.f;
    float mrow[2] = {-1e30f, -1e30f};
    float lrow[2] = {0.f, 0.f};

    for (int kt = 0; kt < 34; kt++) {
        int k0t = kt*64;
        CP_WAIT1();
        __syncthreads();
        if (kt + 2 < 34) {
            int s = (kt+2) % 3;
            ATT_ISSUE(s, (kt+2)*64);
        }
        CP_COMMIT();

        __half* Khs = smb + AQ_ELEMS + (kt%3)*AKV_ELEMS;
        __half* Vhs = Khs + 2560;

        // ---- S = Q K^T (1-term) ----
        float s[8][4];
        #pragma unroll
        for (int i=0;i<8;i++)
            #pragma unroll
            for (int j=0;j<4;j++) s[i][j]=0.f;
        #pragma unroll
        for (int ks = 0; ks < 2; ks++) {
            unsigned ah[4];
            ldsm4(ah[0],ah[1],ah[2],ah[3], sptr(Qhs + arow*40 + ks*16 + akoff));
            unsigned kb[4][4];
            #pragma unroll
            for (int p = 0; p < 4; p++)
                ldsm4(kb[p][0],kb[p][1],kb[p][2],kb[p][3], sptr(Khs + (brow + p*16)*40 + ks*16 + bkoff));
            #pragma unroll
            for (int p = 0; p < 4; p++) {
                mma_f16(s[2*p],   ah, kb[p][0], kb[p][1]);
                mma_f16(s[2*p+1], ah, kb[p][2], kb[p][3]);
            }
        }

        // ---- online softmax in exp2 domain (log2e pre-folded into Q) ----
        int tail = (k0t + 64 > LL);
        float fac[2];
        #pragma unroll
        for (int hf = 0; hf < 2; hf++) {
            float vmax = -1e30f;
            #pragma unroll
            for (int na = 0; na < 8; na++) {
                float v0 = s[na][2*hf];
                float v1 = s[na][2*hf+1];
                if (tail) {
                    if (k0t + na*8 + c2     >= LL) v0 = -1e30f;
                    if (k0t + na*8 + c2 + 1 >= LL) v1 = -1e30f;
                }
                s[na][2*hf] = v0; s[na][2*hf+1] = v1;
                vmax = fmaxf(vmax, fmaxf(v0, v1));
            }
            vmax = fmaxf(vmax, __shfl_xor_sync(0xffffffffu, vmax, 1));
            vmax = fmaxf(vmax, __shfl_xor_sync(0xffffffffu, vmax, 2));
            float mnew = fmaxf(mrow[hf], vmax);
            fac[hf] = exp2f(mrow[hf] - mnew);
            mrow[hf] = mnew;
            float ps = 0.f;
            #pragma unroll
            for (int na = 0; na < 8; na++) {
                float p0 = exp2f(s[na][2*hf]   - mnew);
                float p1 = exp2f(s[na][2*hf+1] - mnew);
                s[na][2*hf] = p0; s[na][2*hf+1] = p1;
                ps += p0 + p1;
            }
            ps += __shfl_xor_sync(0xffffffffu, ps, 1);
            ps += __shfl_xor_sync(0xffffffffu, ps, 2);
            lrow[hf] = lrow[hf]*fac[hf] + ps;
        }

        // ---- pack P fragments ----
        unsigned pah[4][4];
        #pragma unroll
        for (int ks = 0; ks < 4; ks++) {
            pah[ks][0] = packh(s[2*ks][0],   s[2*ks][1]);
            pah[ks][1] = packh(s[2*ks][2],   s[2*ks][3]);
            pah[ks][2] = packh(s[2*ks+1][0], s[2*ks+1][1]);
            pah[ks][3] = packh(s[2*ks+1][2], s[2*ks+1][3]);
        }

        // ---- rescale O ----
        #pragma unroll
        for (int na = 0; na < 4; na++) {
            sO[na][0] *= fac[0]; sO[na][1] *= fac[0];
            sO[na][2] *= fac[1]; sO[na][3] *= fac[1];
        }

        // ---- O += P V ----
        #pragma unroll
        for (int ks = 0; ks < 4; ks++) {
            unsigned vb[2][4];
            #pragma unroll
            for (int p = 0; p < 2; p++)
                ldsm4(vb[p][0],vb[p][1],vb[p][2],vb[p][3], sptr(Vhs + (brow + p*16)*72 + ks*16 + bkoff));
            #pragma unroll
            for (int p = 0; p < 2; p++) {
                mma_f16(sO[2*p],   pah[ks], vb[p][0], vb[p][1]);
                mma_f16(sO[2*p+1], pah[ks], vb[p][2], vb[p][3]);
            }
        }
    }

    // ---- normalize + store single fp16 ----
    int r0 = lane >> 2;
    float inv0 = 1.f / lrow[0];
    float inv1 = 1.f / lrow[1];
    #pragma unroll
    for (int na = 0; na < 4; na++) {
        int col = h*DH + na*8 + c2;
        int qrow = q0 + wid*16 + r0;
        if (qrow < LL) {
            size_t o = (((size_t)(b*LL + qrow))*DD + col) >> 1;
            ((unsigned*)outh)[o] = packh(sO[na][0]*inv0, sO[na][1]*inv0);
        }
        if (qrow + 8 < LL) {
            size_t o = (((size_t)(b*LL + qrow + 8))*DD + col) >> 1;
            ((unsigned*)outh)[o] = packh(sO[na][2]*inv1, sO[na][3]*inv1);
        }
    }
}

// ---------------- residual add + LayerNorm (warp/row) + optional fp16 split
__global__ void __launch_bounds__(256) add_ln_kernel(
    const float* __restrict__ x, const float* __restrict__ y,
    const float* __restrict__ gam, const float* __restrict__ bet,
    float* __restrict__ out, __half* __restrict__ oh, __half* __restrict__ ol,
    int doadd)
{
    int warp = threadIdx.x >> 5, lane = threadIdx.x & 31;
    int row = blockIdx.x*8 + warp;
    const float* xr = x + (size_t)row*DD + lane*8;
    float v[8];
    float4 va = *(const float4*)(xr);
    float4 vb = *(const float4*)(xr + 4);
    v[0]=va.x; v[1]=va.y; v[2]=va.z; v[3]=va.w;
    v[4]=vb.x; v[5]=vb.y; v[6]=vb.z; v[7]=vb.w;
    if (doadd) {
        const float* yr = y + (size_t)row*DD + lane*8;
        float4 ya = *(const float4*)(yr);
        float4 yb = *(const float4*)(yr + 4);
        v[0]+=ya.x; v[1]+=ya.y; v[2]+=ya.z; v[3]+=ya.w;
        v[4]+=yb.x; v[5]+=yb.y; v[6]+=yb.z; v[7]+=yb.w;
    }
    float s = 0.f;
    #pragma unroll
    for (int i=0;i<8;i++) s += v[i];
    #pragma unroll
    for (int off=16; off; off>>=1) s += __shfl_xor_sync(0xffffffffu, s, off);
    float mean = s * (1.f/DD);
    float s2 = 0.f;
    #pragma unroll
    for (int i=0;i<8;i++) { v[i] -= mean; s2 += v[i]*v[i]; }
    #pragma unroll
    for (int off=16; off; off>>=1) s2 += __shfl_xor_sync(0xffffffffu, s2, off);
    float rstd = rsqrtf(s2 * (1.f/DD) + 1e-5f);
    const float* gp = gam + lane*8;
    const float* bp = bet + lane*8;
    float4 ga = *(const float4*)(gp);
    float4 gb = *(const float4*)(gp+4);
    float4 ba = *(const float4*)(bp);
    float4 bb = *(const float4*)(bp+4);
    float g[8] = {ga.x,ga.y,ga.z,ga.w,gb.x,gb.y,gb.z,gb.w};
    float be[8] = {ba.x,ba.y,ba.z,ba.w,bb.x,bb.y,bb.z,bb.w};
    float o[8];
    #pragma unroll
    for (int i=0;i<8;i++) o[i] = v[i]*rstd*g[i] + be[i];
    float* op = out + (size_t)row*DD + lane*8;
    *(float4*)(op)   = make_float4(o[0],o[1],o[2],o[3]);
    *(float4*)(op+4) = make_float4(o[4],o[5],o[6],o[7]);
    if (oh) {
        unsigned hw[4], lw[4];
        split2(o[0],o[1],hw[0],lw[0]);
        split2(o[2],o[3],hw[1],lw[1]);
        split2(o[4],o[5],hw[2],lw[2]);
        split2(o[6],o[7],hw[3],lw[3]);
        size_t ob = ((size_t)row*DD + lane*8) >> 1;
        *(uint4*)((unsigned*)oh + ob) = make_uint4(hw[0],hw[1],hw[2],hw[3]);
        *(uint4*)((unsigned*)ol + ob) = make_uint4(lw[0],lw[1],lw[2],lw[3]);
    }
}

// ---------------- launch ----------------
extern "C" void kernel_launch(void* const* d_in, const int* in_sizes, int n_in,
                              void* d_out, int out_size)
{
    const float* x_img          = (const float*)d_in[0];
    const void*  pmask          = (const void*)d_in[1];
    const int*   valid_idx      = (const int*)d_in[2];
    const float* pe_w           = (const float*)d_in[3];
    const float* pe_b           = (const float*)d_in[4];
    const float* spos           = (const float*)d_in[5];
    const float* Wqkv           = (const float*)d_in[6];
    const float* bqkv           = (const float*)d_in[7];
    const float* Wo             = (const float*)d_in[8];
    const float* bo             = (const float*)d_in[9];
    const float* ln1s           = (const float*)d_in[10];
    const float* ln1b           = (const float*)d_in[11];
    const float* W1             = (const float*)d_in[12];
    const float* b1             = (const float*)d_in[13];
    const float* W2             = (const float*)d_in[14];
    const float* b2             = (const float*)d_in[15];
    const float* ln2s           = (const float*)d_in[16];
    const float* ln2b           = (const float*)d_in[17];
    const float* nfs            = (const float*)d_in[18];
    const float* nfb            = (const float*)d_in[19];
    float* out = (float*)d_out;

    float *px, *py;
    __half *pxh, *pxl, *path, *pffh, *pwh;
    cudaGetSymbolAddress((void**)&px,   g_x);
    cudaGetSymbolAddress((void**)&py,   g_y);
    cudaGetSymbolAddress((void**)&pxh,  g_xh);
    cudaGetSymbolAddress((void**)&pxl,  g_xl);
    cudaGetSymbolAddress((void**)&path, g_atth);
    cudaGetSymbolAddress((void**)&pffh, g_ffh);
    cudaGetSymbolAddress((void**)&pwh,  g_wh);

    cudaFuncSetAttribute(attn_kernel, cudaFuncAttributeMaxDynamicSharedMemorySize, ATT_SMEM);
    cudaFuncSetAttribute(gemm_kernel, cudaFuncAttributeMaxDynamicSharedMemorySize, GEMM_SMEM);

    prep_weights_kernel<<<WTOTAL/256, 256>>>(Wqkv, Wo, W1, W2);
    build_vis_kernel<<<(BB*TT+255)/256, 256>>>(pmask, valid_idx);
    embed_kernel<<<MM/16, 256>>>(x_img, valid_idx, pe_w, pe_b, spos);
    cvt_x_kernel<<<MM*DD/512, 256>>>();

    for (int i = 0; i < NLAYERS; i++) {
        const __half* wh = pwh + (size_t)i*WLAYER;
        // QKV GEMM (A 2-term) with fused Q/K/V^T epilogue
        gemm_kernel<<<dim3(MM/128, 6), 256, GEMM_SMEM>>>(
            pxh, pxl, wh + WOFS_QKV, bqkv + i*768,
            nullptr, nullptr, 768, 256, 0, 2, 2);
        attn_kernel<<<dim3(17, BB*NHEAD), 256, ATT_SMEM>>>(path);
        // Wo GEMM (A 1-term: attention out single fp16)
        gemm_kernel<<<dim3(MM/128, 2), 256, GEMM_SMEM>>>(
            path, nullptr, wh + WOFS_O, bo + i*256,
            py, nullptr, 256, 256, 0, 0, 1);
        add_ln_kernel<<<MM/8, 256>>>(px, py, ln1s + i*DD, ln1b + i*DD, px, pxh, pxl, 1);
        // FF1 GEMM (A 2-term) -> relu -> single fp16
        gemm_kernel<<<dim3(MM/128, 8), 256, GEMM_SMEM>>>(
            pxh, pxl, wh + WOFS_1, b1 + i*DFF,
            nullptr, pffh, 1024, 256, 1, 1, 2);
        // FF2 GEMM (A 1-term)
        gemm_kernel<<<dim3(MM/128, 2), 256, GEMM_SMEM>>>(
            pffh, nullptr, wh + WOFS_2, b2 + i*256,
            py, nullptr, 256, 1024, 0, 0, 1);
        add_ln_kernel<<<MM/8, 256>>>(px, py, ln2s + i*DD, ln2b + i*DD, px, pxh, pxl, 1);
    }
    add_ln_kernel<<<MM/8, 256>>>(px, px, nfs, nfb, out, nullptr, nullptr, 0);
}

// round 15
// speedup vs baseline: 1.5470x; 1.5470x over previous
#include <cuda_runtime.h>
#include <cuda_fp16.h>
#include <math.h>
#include <stdint.h>

#define BB 8
#define TT 90
#define HIMG 290
#define WIMG 180
#define PS 10
#define NWP 18
#define NP 522
#define PD 100
#define NV 94
#define KVIS 24
#define LL 2160
#define DD 256
#define NHEAD 8
#define DH 32
#define NLAYERS 6
#define DFF 1024
#define MM (BB*LL)   /* 17280 */
#define LTP 2176     /* LL padded to 68*32 */
#define QSCALE (0.17677669529663687f * 1.4426950408889634f)  /* fold log2e */

// per-layer weight segment offsets (elements), layer stride
#define WOFS_QKV 0
#define WOFS_O   196608
#define WOFS_1   262144
#define WOFS_2   524288
#define WLAYER   786432
#define WTOTAL   (6*WLAYER)

// ---------------- scratch (no cudaMalloc allowed) ----------------
__device__ float g_x[MM*DD];
__device__ float g_y[MM*DD];
__device__ __half g_xh[MM*DD],  g_xl[MM*DD];
__device__ __half g_atth[MM*DD];                   // attention out, single fp16
__device__ __half g_ffh[MM*DFF];                   // FF1 out, single fp16
__device__ __half g_qh[BB*NHEAD*LL*DH];            // Q single fp16 (pre-scaled)
__device__ __half g_kh[BB*NHEAD*LL*DH];            // K single fp16
__device__ __half g_vth[BB*NHEAD*DH*LTP];          // V single fp16, transposed
__device__ __half g_wh[WTOTAL];                    // weights single fp16
__device__ int   g_tokv[MM];

// ---------------- helpers ----------------
__device__ __forceinline__ unsigned sptr(const void* p) {
    return (unsigned)__cvta_generic_to_shared(p);
}
__device__ __forceinline__ void ldsm4(unsigned &r0, unsigned &r1, unsigned &r2, unsigned &r3, unsigned addr) {
    asm volatile("ldmatrix.sync.aligned.m8n8.x4.shared.b16 {%0,%1,%2,%3}, [%4];"
                 : "=r"(r0), "=r"(r1), "=r"(r2), "=r"(r3) : "r"(addr));
}
__device__ __forceinline__ void mma_f16(float* c, const unsigned* a, unsigned b0, unsigned b1) {
    asm volatile("mma.sync.aligned.m16n8k16.row.col.f32.f16.f16.f32 "
                 "{%0,%1,%2,%3}, {%4,%5,%6,%7}, {%8,%9}, {%0,%1,%2,%3};"
                 : "+f"(c[0]), "+f"(c[1]), "+f"(c[2]), "+f"(c[3])
                 : "r"(a[0]), "r"(a[1]), "r"(a[2]), "r"(a[3]), "r"(b0), "r"(b1));
}
// split two f32 into packed fp16 hi and lo words
__device__ __forceinline__ void split2(float x0, float x1, unsigned &h, unsigned &l) {
    __half h0 = __float2half_rn(x0), h1 = __float2half_rn(x1);
    float r0 = x0 - __half2float(h0), r1 = x1 - __half2float(h1);
    __half l0 = __float2half_rn(r0), l1 = __float2half_rn(r1);
    h = (unsigned)__half_as_ushort(h0) | ((unsigned)__half_as_ushort(h1) << 16);
    l = (unsigned)__half_as_ushort(l0) | ((unsigned)__half_as_ushort(l1) << 16);
}
// pack two f32 as fp16 pair (hi only)
__device__ __forceinline__ unsigned packh(float x0, float x1) {
    __half h0 = __float2half_rn(x0), h1 = __float2half_rn(x1);
    return (unsigned)__half_as_ushort(h0) | ((unsigned)__half_as_ushort(h1) << 16);
}
__device__ __forceinline__ void cp16(uint32_t dst, const void* src) {
    asm volatile("cp.async.cg.shared.global [%0], [%1], 16;" :: "r"(dst), "l"(src) : "memory");
}
__device__ __forceinline__ void cp16p(uint32_t dst, const void* src, int pred) {
    int sz = pred ? 16 : 0;
    asm volatile("cp.async.cg.shared.global [%0], [%1], 16, %2;" :: "r"(dst), "l"(src), "r"(sz) : "memory");
}
#define CP_COMMIT() asm volatile("cp.async.commit_group;" ::: "memory")
#define CP_WAIT1()  asm volatile("cp.async.wait_group 1;" ::: "memory")

// ---------------- token list ----------------
__global__ void build_vis_kernel(const void* __restrict__ mask_raw,
                                 const int* __restrict__ valid_idx)
{
    int bt = blockIdx.x*blockDim.x + threadIdx.x;
    if (bt >= BB*TT) return;
    const int*   mi = (const int*)mask_raw;
    const float* mf = (const float*)mask_raw;
    const unsigned char* mb = (const unsigned char*)mask_raw;
    int is_int = 1;
    for (int j = 0; j < NP; j++) { int w = mi[j]; if (w != 0 && w != 1) { is_int = 0; break; } }
    int is_float = 0;
    if (!is_int) {
        is_float = 1;
        for (int j = 0; j < NP; j++) { float w = mf[j]; if (w != 0.0f && w != 1.0f) { is_float = 0; break; } }
    }
    int base = bt*KVIS, cnt = 0;
    for (int v = 0; v < NV; v++) {
        int idx = bt*NP + valid_idx[v];
        int masked;
        if (is_int)        masked = (mi[idx] != 0);
        else if (is_float) masked = (mf[idx] != 0.0f);
        else               masked = (mb[idx] != 0);
        if (!masked) { if (cnt < KVIS) g_tokv[base+cnt] = v; cnt++; }
    }
}

// ---------------- patchify + patch embed + pos encodings ----------------
__global__ void __launch_bounds__(256) embed_kernel(
    const float* __restrict__ img, const int* __restrict__ valid_idx,
    const float* __restrict__ Wpe, const float* __restrict__ bpe,
    const float* __restrict__ spos)
{
    __shared__ float pix[16][PD];
    __shared__ float wsm[DD][27];
    __shared__ int sm_v[16], sm_t[16], sm_off[16];
    int tid = threadIdx.x;
    int m0 = blockIdx.x * 16;
    if (tid < 16) {
        int m = m0 + tid;
        int b = m / LL;
        int l = m - b*LL;
        int t = l / KVIS;
        int v = g_tokv[m];
        int patch = valid_idx[v];
        int hp = patch / NWP, wp = patch - hp*NWP;
        sm_v[tid] = v; sm_t[tid] = t;
        sm_off[tid] = ((b*TT + t)*HIMG + hp*PS)*WIMG + wp*PS;
    }
    __syncthreads();
    for (int j = tid; j < 16*PD; j += 256) {
        int tok = j / PD, pd = j - tok*PD;
        int ph = pd / PS, pw = pd - ph*PS;
        pix[tok][pd] = img[sm_off[tok] + ph*WIMG + pw];
    }
    float acc[16];
    #pragma unroll
    for (int i = 0; i < 16; i++) acc[i] = 0.f;
    for (int k0 = 0; k0 < PD; k0 += 25) {
        __syncthreads();
        for (int j = tid; j < DD*25; j += 256) {
            int dd = j / 25, kk = j - dd*25;
            wsm[dd][kk] = Wpe[dd*PD + k0 + kk];
        }
        __syncthreads();
        #pragma unroll
        for (int kk = 0; kk < 25; kk++) {
            float w = wsm[tid][kk];
            #pragma unroll
            for (int tok = 0; tok < 16; tok++)
                acc[tok] = fmaf(w, pix[tok][k0+kk], acc[tok]);
        }
    }
    int d = tid;
    float freq = expf((float)(d & ~1) * (-9.210340371976184f / 256.f));
    float pb = bpe[d];
    #pragma unroll
    for (int tok = 0; tok < 16; tok++) {
        float val = (float)sm_t[tok] * freq;
        float pe = (d & 1) ? cosf(val) : sinf(val);
        g_x[(m0+tok)*DD + d] = acc[tok] + pb + spos[sm_v[tok]*DD + d] + pe;
    }
}

// ---------------- one-time prep: weights -> single fp16, layer-major -------
__global__ void prep_weights_kernel(const float* __restrict__ Wqkv, const float* __restrict__ Wo,
                                    const float* __restrict__ W1, const float* __restrict__ W2)
{
    int i = blockIdx.x*blockDim.x + threadIdx.x;
    int layer = i / WLAYER;
    int r = i - layer*WLAYER;
    float v;
    if      (r < WOFS_O) v = Wqkv[layer*196608 + r];
    else if (r < WOFS_1) v = Wo[layer*65536 + r - WOFS_O];
    else if (r < WOFS_2) v = W1[layer*262144 + r - WOFS_1];
    else                 v = W2[layer*262144 + r - WOFS_2];
    g_wh[i] = __float2half_rn(v);
}

// ---------------- x fp32 -> hi/lo fp16 (after embed only) ----------------
__global__ void cvt_x_kernel()
{
    int i = blockIdx.x*blockDim.x + threadIdx.x;   // over MM*DD/2
    float2 v = ((const float2*)g_x)[i];
    unsigned h, l; split2(v.x, v.y, h, l);
    ((unsigned*)g_xh)[i] = h;
    ((unsigned*)g_xl)[i] = l;
}

// ---------------- fp16 tensor-core GEMM, 3-stage cp.async ring -------------
// C[m,n] = sum_k A[m,k]*W[n,k] + bias[n].  A ATERMS-term (template), W single.
// smem slots per stage: 0=Ah, 1=Wh, [2=Al when ATERMS==2].
// OUTMODE: 0 fp32 C; 1 fp16 Ch; 2 fused QKV epilogue.
#define GSTR 24
#define GARR (128*GSTR)
#define GSTAGE (3*GARR)
#define GEMM_SMEM (3*GSTAGE*2)

template<int ATERMS, int OUTMODE, int RELU>
__global__ void __launch_bounds__(256,2) gemm_kernel(
    const __half* __restrict__ Ahg, const __half* __restrict__ Alg,
    const __half* __restrict__ Whg,
    const float* __restrict__ bias,
    float* __restrict__ C, __half* __restrict__ Ch,
    int Ndim, int Kdim)
{
    constexpr int NARR = ATERMS + 1;
    extern __shared__ __align__(16) char smraw[];
    __half* smb = (__half*)smraw;
    uint32_t smb_u = sptr(smraw);
    int tid = threadIdx.x, lane = tid & 31, wid = tid >> 5;
    int wm = wid >> 1, wn = wid & 1;
    int m0 = blockIdx.x*128, n0 = blockIdx.y*128;

    const __half* srcs[3];
    srcs[0] = Ahg + (size_t)m0*Kdim;
    srcs[1] = Whg + (size_t)n0*Kdim;
    srcs[2] = (ATERMS == 2) ? (Alg + (size_t)m0*Kdim) : srcs[0];

    float acc[2][8][4];
    #pragma unroll
    for (int i=0;i<2;i++)
        #pragma unroll
        for (int j=0;j<8;j++)
            #pragma unroll
            for (int q=0;q<4;q++) acc[i][j][q]=0.f;

    int arow = wm*32 + (lane & 15);
    int akoff = (lane >> 4) << 3;
    int brow = wn*64 + ((lane >> 4) << 3) + (lane & 7);
    int bkoff = ((lane >> 3) & 1) << 3;

    #define GEMM_ISSUE(s, k0) do { \
        uint32_t base_ = smb_u + (s)*GSTAGE*2; \
        _Pragma("unroll") \
        for (int it_ = 0; it_ < NARR; it_++) { \
            int idx_ = it_*256 + tid; \
            int arr_ = idx_ >> 8, rem_ = idx_ & 255; \
            int row_ = rem_ >> 1, ch_ = rem_ & 1; \
            const void* gp_ = srcs[arr_] + (size_t)row_*Kdim + (k0) + ch_*8; \
            uint32_t dst_ = base_ + (arr_*GARR + row_*GSTR + ch_*8)*2; \
            cp16(dst_, gp_); \
        } \
    } while(0)

    GEMM_ISSUE(0, 0);  CP_COMMIT();
    GEMM_ISSUE(1, 16); CP_COMMIT();

    int NTK = Kdim >> 4;
    for (int t = 0; t < NTK; t++) {
        CP_WAIT1();
        __syncthreads();
        if (t + 2 < NTK) {
            int s = (t+2) % 3;
            GEMM_ISSUE(s, (t+2)*16);
        }
        CP_COMMIT();

        __half* Ah = smb + (t%3)*GSTAGE;
        __half* Wh = Ah + GARR;
        __half* Al = Wh + GARR;

        unsigned ah0[4], ah1[4];
        ldsm4(ah0[0],ah0[1],ah0[2],ah0[3], sptr(Ah + arow*GSTR + akoff));
        ldsm4(ah1[0],ah1[1],ah1[2],ah1[3], sptr(Ah + (arow+16)*GSTR + akoff));

        unsigned bf[4][4];
        #pragma unroll
        for (int p = 0; p < 4; p++)
            ldsm4(bf[p][0],bf[p][1],bf[p][2],bf[p][3], sptr(Wh + (brow + p*16)*GSTR + bkoff));
        // pass 1: Ah x Wh
        #pragma unroll
        for (int p = 0; p < 4; p++) {
            mma_f16(acc[0][2*p],   ah0, bf[p][0], bf[p][1]);
            mma_f16(acc[0][2*p+1], ah0, bf[p][2], bf[p][3]);
            mma_f16(acc[1][2*p],   ah1, bf[p][0], bf[p][1]);
            mma_f16(acc[1][2*p+1], ah1, bf[p][2], bf[p][3]);
        }
        // pass 2: Al x Wh (compile-time)
        if (ATERMS == 2) {
            unsigned al0[4], al1[4];
            ldsm4(al0[0],al0[1],al0[2],al0[3], sptr(Al + arow*GSTR + akoff));
            ldsm4(al1[0],al1[1],al1[2],al1[3], sptr(Al + (arow+16)*GSTR + akoff));
            #pragma unroll
            for (int p = 0; p < 4; p++) {
                mma_f16(acc[0][2*p],   al0, bf[p][0], bf[p][1]);
                mma_f16(acc[0][2*p+1], al0, bf[p][2], bf[p][3]);
                mma_f16(acc[1][2*p],   al1, bf[p][0], bf[p][1]);
                mma_f16(acc[1][2*p+1], al1, bf[p][2], bf[p][3]);
            }
        }
        __syncthreads();
    }

    // epilogue
    int r0 = lane >> 2;
    int c2 = (lane & 3) << 1;
    #pragma unroll
    for (int ma = 0; ma < 2; ma++) {
        #pragma unroll
        for (int na = 0; na < 8; na++) {
            int col = n0 + wn*64 + na*8 + c2;
            float2 bsv = *(const float2*)(bias + col);
            float v0 = acc[ma][na][0] + bsv.x;
            float v1 = acc[ma][na][1] + bsv.y;
            float v2 = acc[ma][na][2] + bsv.x;
            float v3 = acc[ma][na][3] + bsv.y;
            int row = m0 + wm*32 + ma*16 + r0;
            if (OUTMODE == 2) {
                // fused QKV: seg 0=Q(scaled,single), 1=K(single), 2=V^T(single)
                int seg = col >> 8;
                int h = (col >> 5) & 7;
                int dh = col & 31;
                if (seg == 0) { v0 *= QSCALE; v1 *= QSCALE; v2 *= QSCALE; v3 *= QSCALE; }
                #pragma unroll
                for (int half = 0; half < 2; half++) {
                    int rr = row + half*8;
                    float a0 = half ? v2 : v0;
                    float a1 = half ? v3 : v1;
                    int bb = rr / LL;
                    int l = rr - bb*LL;
                    int bh = bb*8 + h;
                    if (seg < 2) {
                        size_t o = ((size_t)bh*LL + l)*16 + (dh >> 1);
                        ((unsigned*)(seg == 0 ? g_qh : g_kh))[o] = packh(a0, a1);
                    } else {
                        size_t o0 = ((size_t)bh*32 + dh)*LTP + l;
                        size_t o1 = ((size_t)bh*32 + dh + 1)*LTP + l;
                        g_vth[o0] = __float2half_rn(a0);
                        g_vth[o1] = __float2half_rn(a1);
                    }
                }
            } else {
                if (RELU) {
                    v0 = fmaxf(v0,0.f); v1 = fmaxf(v1,0.f);
                    v2 = fmaxf(v2,0.f); v3 = fmaxf(v3,0.f);
                }
                if (OUTMODE == 1) {
                    size_t o = ((size_t)row*Ndim + col) >> 1;
                    ((unsigned*)Ch)[o] = packh(v0, v1);
                    o = ((size_t)(row+8)*Ndim + col) >> 1;
                    ((unsigned*)Ch)[o] = packh(v2, v3);
                } else {
                    *(float2*)(C + (size_t)row*Ndim + col) = make_float2(v0, v1);
                    *(float2*)(C + (size_t)(row+8)*Ndim + col) = make_float2(v2, v3);
                }
            }
        }
    }
}

// ---------------- flash attention, pure fp16 operands, exp2 softmax --------
// QK 1-term (Qh x Kh), PV 1-term (Ph x Vh). Logits in log2 units.
#define AQ_ELEMS (128*40)
#define AKV_ELEMS 4864
#define ATT_SMEM ((AQ_ELEMS + 3*AKV_ELEMS)*2)

__global__ void __launch_bounds__(256,2) attn_kernel(__half* __restrict__ outh)
{
    extern __shared__ __align__(16) char smraw[];
    __half* smb = (__half*)smraw;
    uint32_t smb_u = sptr(smraw);
    __half* Qhs = smb;                 // [128][40]

    int tid = threadIdx.x, lane = tid & 31, wid = tid >> 5;
    int q0 = blockIdx.x * 128;
    int bh = blockIdx.y;
    int b = bh >> 3, h = bh & 7;

    #define ATT_ISSUE(s, k0t) do { \
        uint32_t sb_ = smb_u + (AQ_ELEMS + (s)*AKV_ELEMS)*2; \
        _Pragma("unroll") \
        for (int it_ = 0; it_ < 2; it_++) { \
            int idx_ = it_*256 + tid; \
            if (idx_ < 256) { \
                int r_ = idx_ >> 2, c_ = idx_ & 3; \
                int krow_ = (k0t) + r_; \
                int pred_ = (krow_ < LL); \
                int kc_ = pred_ ? krow_ : 0; \
                const __half* src_ = g_kh + ((size_t)bh*LL + kc_)*32 + c_*8; \
                uint32_t dst_ = sb_ + (r_*40 + c_*8)*2; \
                cp16p(dst_, src_, pred_); \
            } else { \
                int j_ = idx_ - 256; \
                int dd_ = j_ >> 3, c_ = j_ & 7; \
                const __half* src_ = g_vth + ((size_t)bh*32 + dd_)*LTP + (k0t) + c_*8; \
                uint32_t dst_ = sb_ + (2560 + dd_*72 + c_*8)*2; \
                cp16(dst_, src_); \
            } \
        } \
    } while(0)

    // ---- Q copy via cp.async ----
    #pragma unroll
    for (int it = 0; it < 2; it++) {
        int idx = it*256 + tid;
        int r = idx >> 2, c = idx & 3;
        int qrow = q0 + r;
        int pred = (qrow < LL);
        int qc = pred ? qrow : 0;
        const __half* src = g_qh + ((size_t)bh*LL + qc)*32 + c*8;
        uint32_t dst = smb_u + (r*40 + c*8)*2;
        cp16p(dst, src, pred);
    }
    ATT_ISSUE(0, 0);  CP_COMMIT();
    ATT_ISSUE(1, 64); CP_COMMIT();

    int arow = wid*16 + (lane & 15);
    int akoff = (lane >> 4) << 3;
    int brow = ((lane >> 4) << 3) + (lane & 7);
    int bkoff = ((lane >> 3) & 1) << 3;
    int c2 = (lane & 3) << 1;

    float sO[4][4];
    #pragma unroll
    for (int i=0;i<4;i++)
        #pragma unroll
        for (int j=0;j<4;j++) sO[i][j]=0.f;
    float mrow[2] = {-1e30f, -1e30f};
    float lrow[2] = {0.f, 0.f};

    for (int kt = 0; kt < 34; kt++) {
        int k0t = kt*64;
        CP_WAIT1();
        __syncthreads();
        if (kt + 2 < 34) {
            int s = (kt+2) % 3;
            ATT_ISSUE(s, (kt+2)*64);
        }
        CP_COMMIT();

        __half* Khs = smb + AQ_ELEMS + (kt%3)*AKV_ELEMS;
        __half* Vhs = Khs + 2560;

        // ---- S = Q K^T (1-term) ----
        float s[8][4];
        #pragma unroll
        for (int i=0;i<8;i++)
            #pragma unroll
            for (int j=0;j<4;j++) s[i][j]=0.f;
        #pragma unroll
        for (int ks = 0; ks < 2; ks++) {
            unsigned ah[4];
            ldsm4(ah[0],ah[1],ah[2],ah[3], sptr(Qhs + arow*40 + ks*16 + akoff));
            unsigned kb[4][4];
            #pragma unroll
            for (int p = 0; p < 4; p++)
                ldsm4(kb[p][0],kb[p][1],kb[p][2],kb[p][3], sptr(Khs + (brow + p*16)*40 + ks*16 + bkoff));
            #pragma unroll
            for (int p = 0; p < 4; p++) {
                mma_f16(s[2*p],   ah, kb[p][0], kb[p][1]);
                mma_f16(s[2*p+1], ah, kb[p][2], kb[p][3]);
            }
        }

        // ---- online softmax in exp2 domain (log2e pre-folded into Q) ----
        int tail = (k0t + 64 > LL);
        float fac[2];
        #pragma unroll
        for (int hf = 0; hf < 2; hf++) {
            float vmax = -1e30f;
            #pragma unroll
            for (int na = 0; na < 8; na++) {
                float v0 = s[na][2*hf];
                float v1 = s[na][2*hf+1];
                if (tail) {
                    if (k0t + na*8 + c2     >= LL) v0 = -1e30f;
                    if (k0t + na*8 + c2 + 1 >= LL) v1 = -1e30f;
                }
                s[na][2*hf] = v0; s[na][2*hf+1] = v1;
                vmax = fmaxf(vmax, fmaxf(v0, v1));
            }
            vmax = fmaxf(vmax, __shfl_xor_sync(0xffffffffu, vmax, 1));
            vmax = fmaxf(vmax, __shfl_xor_sync(0xffffffffu, vmax, 2));
            float mnew = fmaxf(mrow[hf], vmax);
            fac[hf] = exp2f(mrow[hf] - mnew);
            mrow[hf] = mnew;
            float ps = 0.f;
            #pragma unroll
            for (int na = 0; na < 8; na++) {
                float p0 = exp2f(s[na][2*hf]   - mnew);
                float p1 = exp2f(s[na][2*hf+1] - mnew);
                s[na][2*hf] = p0; s[na][2*hf+1] = p1;
                ps += p0 + p1;
            }
            ps += __shfl_xor_sync(0xffffffffu, ps, 1);
            ps += __shfl_xor_sync(0xffffffffu, ps, 2);
            lrow[hf] = lrow[hf]*fac[hf] + ps;
        }

        // ---- pack P fragments ----
        unsigned pah[4][4];
        #pragma unroll
        for (int ks = 0; ks < 4; ks++) {
            pah[ks][0] = packh(s[2*ks][0],   s[2*ks][1]);
            pah[ks][1] = packh(s[2*ks][2],   s[2*ks][3]);
            pah[ks][2] = packh(s[2*ks+1][0], s[2*ks+1][1]);
            pah[ks][3] = packh(s[2*ks+1][2], s[2*ks+1][3]);
        }

        // ---- rescale O ----
        #pragma unroll
        for (int na = 0; na < 4; na++) {
            sO[na][0] *= fac[0]; sO[na][1] *= fac[0];
            sO[na][2] *= fac[1]; sO[na][3] *= fac[1];
        }

        // ---- O += P V ----
        #pragma unroll
        for (int ks = 0; ks < 4; ks++) {
            unsigned vb[2][4];
            #pragma unroll
            for (int p = 0; p < 2; p++)
                ldsm4(vb[p][0],vb[p][1],vb[p][2],vb[p][3], sptr(Vhs + (brow + p*16)*72 + ks*16 + bkoff));
            #pragma unroll
            for (int p = 0; p < 2; p++) {
                mma_f16(sO[2*p],   pah[ks], vb[p][0], vb[p][1]);
                mma_f16(sO[2*p+1], pah[ks], vb[p][2], vb[p][3]);
            }
        }
    }

    // ---- normalize + store single fp16 ----
    int r0 = lane >> 2;
    float inv0 = 1.f / lrow[0];
    float inv1 = 1.f / lrow[1];
    #pragma unroll
    for (int na = 0; na < 4; na++) {
        int col = h*DH + na*8 + c2;
        int qrow = q0 + wid*16 + r0;
        if (qrow < LL) {
            size_t o = (((size_t)(b*LL + qrow))*DD + col) >> 1;
            ((unsigned*)outh)[o] = packh(sO[na][0]*inv0, sO[na][1]*inv0);
        }
        if (qrow + 8 < LL) {
            size_t o = (((size_t)(b*LL + qrow + 8))*DD + col) >> 1;
            ((unsigned*)outh)[o] = packh(sO[na][2]*inv1, sO[na][3]*inv1);
        }
    }
}

// ---------------- residual add + LayerNorm (warp/row) + optional fp16 split
__global__ void __launch_bounds__(256) add_ln_kernel(
    const float* __restrict__ x, const float* __restrict__ y,
    const float* __restrict__ gam, const float* __restrict__ bet,
    float* __restrict__ out, __half* __restrict__ oh, __half* __restrict__ ol,
    int doadd)
{
    int warp = threadIdx.x >> 5, lane = threadIdx.x & 31;
    int row = blockIdx.x*8 + warp;
    const float* xr = x + (size_t)row*DD + lane*8;
    float v[8];
    float4 va = *(const float4*)(xr);
    float4 vb = *(const float4*)(xr + 4);
    v[0]=va.x; v[1]=va.y; v[2]=va.z; v[3]=va.w;
    v[4]=vb.x; v[5]=vb.y; v[6]=vb.z; v[7]=vb.w;
    if (doadd) {
        const float* yr = y + (size_t)row*DD + lane*8;
        float4 ya = *(const float4*)(yr);
        float4 yb = *(const float4*)(yr + 4);
        v[0]+=ya.x; v[1]+=ya.y; v[2]+=ya.z; v[3]+=ya.w;
        v[4]+=yb.x; v[5]+=yb.y; v[6]+=yb.z; v[7]+=yb.w;
    }
    float s = 0.f;
    #pragma unroll
    for (int i=0;i<8;i++) s += v[i];
    #pragma unroll
    for (int off=16; off; off>>=1) s += __shfl_xor_sync(0xffffffffu, s, off);
    float mean = s * (1.f/DD);
    float s2 = 0.f;
    #pragma unroll
    for (int i=0;i<8;i++) { v[i] -= mean; s2 += v[i]*v[i]; }
    #pragma unroll
    for (int off=16; off; off>>=1) s2 += __shfl_xor_sync(0xffffffffu, s2, off);
    float rstd = rsqrtf(s2 * (1.f/DD) + 1e-5f);
    const float* gp = gam + lane*8;
    const float* bp = bet + lane*8;
    float4 ga = *(const float4*)(gp);
    float4 gb = *(const float4*)(gp+4);
    float4 ba = *(const float4*)(bp);
    float4 bb = *(const float4*)(bp+4);
    float g[8] = {ga.x,ga.y,ga.z,ga.w,gb.x,gb.y,gb.z,gb.w};
    float be[8] = {ba.x,ba.y,ba.z,ba.w,bb.x,bb.y,bb.z,bb.w};
    float o[8];
    #pragma unroll
    for (int i=0;i<8;i++) o[i] = v[i]*rstd*g[i] + be[i];
    float* op = out + (size_t)row*DD + lane*8;
    *(float4*)(op)   = make_float4(o[0],o[1],o[2],o[3]);
    *(float4*)(op+4) = make_float4(o[4],o[5],o[6],o[7]);
    if (oh) {
        unsigned hw[4], lw[4];
        split2(o[0],o[1],hw[0],lw[0]);
        split2(o[2],o[3],hw[1],lw[1]);
        split2(o[4],o[5],hw[2],lw[2]);
        split2(o[6],o[7],hw[3],lw[3]);
        size_t ob = ((size_t)row*DD + lane*8) >> 1;
        *(uint4*)((unsigned*)oh + ob) = make_uint4(hw[0],hw[1],hw[2],hw[3]);
        *(uint4*)((unsigned*)ol + ob) = make_uint4(lw[0],lw[1],lw[2],lw[3]);
    }
}

// ---------------- launch ----------------
extern "C" void kernel_launch(void* const* d_in, const int* in_sizes, int n_in,
                              void* d_out, int out_size)
{
    const float* x_img          = (const float*)d_in[0];
    const void*  pmask          = (const void*)d_in[1];
    const int*   valid_idx      = (const int*)d_in[2];
    const float* pe_w           = (const float*)d_in[3];
    const float* pe_b           = (const float*)d_in[4];
    const float* spos           = (const float*)d_in[5];
    const float* Wqkv           = (const float*)d_in[6];
    const float* bqkv           = (const float*)d_in[7];
    const float* Wo             = (const float*)d_in[8];
    const float* bo             = (const float*)d_in[9];
    const float* ln1s           = (const float*)d_in[10];
    const float* ln1b           = (const float*)d_in[11];
    const float* W1             = (const float*)d_in[12];
    const float* b1             = (const float*)d_in[13];
    const float* W2             = (const float*)d_in[14];
    const float* b2             = (const float*)d_in[15];
    const float* ln2s           = (const float*)d_in[16];
    const float* ln2b           = (const float*)d_in[17];
    const float* nfs            = (const float*)d_in[18];
    const float* nfb            = (const float*)d_in[19];
    float* out = (float*)d_out;

    float *px, *py;
    __half *pxh, *pxl, *path, *pffh, *pwh;
    cudaGetSymbolAddress((void**)&px,   g_x);
    cudaGetSymbolAddress((void**)&py,   g_y);
    cudaGetSymbolAddress((void**)&pxh,  g_xh);
    cudaGetSymbolAddress((void**)&pxl,  g_xl);
    cudaGetSymbolAddress((void**)&path, g_atth);
    cudaGetSymbolAddress((void**)&pffh, g_ffh);
    cudaGetSymbolAddress((void**)&pwh,  g_wh);

    cudaFuncSetAttribute(attn_kernel, cudaFuncAttributeMaxDynamicSharedMemorySize, ATT_SMEM);
    cudaFuncSetAttribute(gemm_kernel<2,2,0>, cudaFuncAttributeMaxDynamicSharedMemorySize, GEMM_SMEM);
    cudaFuncSetAttribute(gemm_kernel<1,0,0>, cudaFuncAttributeMaxDynamicSharedMemorySize, GEMM_SMEM);
    cudaFuncSetAttribute(gemm_kernel<2,1,1>, cudaFuncAttributeMaxDynamicSharedMemorySize, GEMM_SMEM);

    prep_weights_kernel<<<WTOTAL/256, 256>>>(Wqkv, Wo, W1, W2);
    build_vis_kernel<<<(BB*TT+255)/256, 256>>>(pmask, valid_idx);
    embed_kernel<<<MM/16, 256>>>(x_img, valid_idx, pe_w, pe_b, spos);
    cvt_x_kernel<<<MM*DD/512, 256>>>();

    for (int i = 0; i < NLAYERS; i++) {
        const __half* wh = pwh + (size_t)i*WLAYER;
        // QKV GEMM (A 2-term) with fused Q/K/V^T epilogue
        gemm_kernel<2,2,0><<<dim3(MM/128, 6), 256, GEMM_SMEM>>>(
            pxh, pxl, wh + WOFS_QKV, bqkv + i*768,
            nullptr, nullptr, 768, 256);
        attn_kernel<<<dim3(17, BB*NHEAD), 256, ATT_SMEM>>>(path);
        // Wo GEMM (A 1-term: attention out single fp16)
        gemm_kernel<1,0,0><<<dim3(MM/128, 2), 256, GEMM_SMEM>>>(
            path, nullptr, wh + WOFS_O, bo + i*256,
            py, nullptr, 256, 256);
        add_ln_kernel<<<MM/8, 256>>>(px, py, ln1s + i*DD, ln1b + i*DD, px, pxh, pxl, 1);
        // FF1 GEMM (A 2-term) -> relu -> single fp16
        gemm_kernel<2,1,1><<<dim3(MM/128, 8), 256, GEMM_SMEM>>>(
            pxh, pxl, wh + WOFS_1, b1 + i*DFF,
            nullptr, pffh, 1024, 256);
        // FF2 GEMM (A 1-term)
        gemm_kernel<1,0,0><<<dim3(MM/128, 2), 256, GEMM_SMEM>>>(
            pffh, nullptr, wh + WOFS_2, b2 + i*256,
            py, nullptr, 256, 1024);
        add_ln_kernel<<<MM/8, 256>>>(px, py, ln2s + i*DD, ln2b + i*DD, px, pxh, pxl, 1);
    }
    add_ln_kernel<<<MM/8, 256>>>(px, px, nfs, nfb, out, nullptr, nullptr, 0);
}

// round 16
// speedup vs baseline: 1.7090x; 1.1047x over previous
#include <cuda_runtime.h>
#include <cuda_fp16.h>
#include <math.h>
#include <stdint.h>

#define BB 8
#define TT 90
#define HIMG 290
#define WIMG 180
#define PS 10
#define NWP 18
#define NP 522
#define PD 100
#define NV 94
#define KVIS 24
#define LL 2160
#define DD 256
#define NHEAD 8
#define DH 32
#define NLAYERS 6
#define DFF 1024
#define MM (BB*LL)   /* 17280 */
#define LTP 2176     /* LL padded to 68*32 */
#define QSCALE (0.17677669529663687f * 1.4426950408889634f)  /* fold log2e */

// per-layer weight segment offsets (elements), layer stride
#define WOFS_QKV 0
#define WOFS_O   196608
#define WOFS_1   262144
#define WOFS_2   524288
#define WLAYER   786432
#define WTOTAL   (6*WLAYER)

// ---------------- scratch (no cudaMalloc allowed) ----------------
__device__ float g_x[MM*DD];
__device__ float g_y[MM*DD];
__device__ __half g_xh[MM*DD];                     // x single fp16
__device__ __half g_atth[MM*DD];                   // attention out, single fp16
__device__ __half g_ffh[MM*DFF];                   // FF1 out, single fp16
__device__ __half g_qh[BB*NHEAD*LL*DH];            // Q single fp16 (pre-scaled)
__device__ __half g_kh[BB*NHEAD*LL*DH];            // K single fp16
__device__ __half g_vth[BB*NHEAD*DH*LTP];          // V single fp16, transposed
__device__ __half g_wh[WTOTAL];                    // weights single fp16
__device__ int   g_tokv[MM];

// ---------------- helpers ----------------
__device__ __forceinline__ unsigned sptr(const void* p) {
    return (unsigned)__cvta_generic_to_shared(p);
}
__device__ __forceinline__ void ldsm4(unsigned &r0, unsigned &r1, unsigned &r2, unsigned &r3, unsigned addr) {
    asm volatile("ldmatrix.sync.aligned.m8n8.x4.shared.b16 {%0,%1,%2,%3}, [%4];"
                 : "=r"(r0), "=r"(r1), "=r"(r2), "=r"(r3) : "r"(addr));
}
__device__ __forceinline__ void mma_f16(float* c, const unsigned* a, unsigned b0, unsigned b1) {
    asm volatile("mma.sync.aligned.m16n8k16.row.col.f32.f16.f16.f32 "
                 "{%0,%1,%2,%3}, {%4,%5,%6,%7}, {%8,%9}, {%0,%1,%2,%3};"
                 : "+f"(c[0]), "+f"(c[1]), "+f"(c[2]), "+f"(c[3])
                 : "r"(a[0]), "r"(a[1]), "r"(a[2]), "r"(a[3]), "r"(b0), "r"(b1));
}
// pack two f32 as fp16 pair
__device__ __forceinline__ unsigned packh(float x0, float x1) {
    __half h0 = __float2half_rn(x0), h1 = __float2half_rn(x1);
    return (unsigned)__half_as_ushort(h0) | ((unsigned)__half_as_ushort(h1) << 16);
}
__device__ __forceinline__ void cp16(uint32_t dst, const void* src) {
    asm volatile("cp.async.cg.shared.global [%0], [%1], 16;" :: "r"(dst), "l"(src) : "memory");
}
__device__ __forceinline__ void cp16p(uint32_t dst, const void* src, int pred) {
    int sz = pred ? 16 : 0;
    asm volatile("cp.async.cg.shared.global [%0], [%1], 16, %2;" :: "r"(dst), "l"(src), "r"(sz) : "memory");
}
#define CP_COMMIT() asm volatile("cp.async.commit_group;" ::: "memory")
#define CP_WAIT1()  asm volatile("cp.async.wait_group 1;" ::: "memory")

// ---------------- token list ----------------
__global__ void build_vis_kernel(const void* __restrict__ mask_raw,
                                 const int* __restrict__ valid_idx)
{
    int bt = blockIdx.x*blockDim.x + threadIdx.x;
    if (bt >= BB*TT) return;
    const int*   mi = (const int*)mask_raw;
    const float* mf = (const float*)mask_raw;
    const unsigned char* mb = (const unsigned char*)mask_raw;
    int is_int = 1;
    for (int j = 0; j < NP; j++) { int w = mi[j]; if (w != 0 && w != 1) { is_int = 0; break; } }
    int is_float = 0;
    if (!is_int) {
        is_float = 1;
        for (int j = 0; j < NP; j++) { float w = mf[j]; if (w != 0.0f && w != 1.0f) { is_float = 0; break; } }
    }
    int base = bt*KVIS, cnt = 0;
    for (int v = 0; v < NV; v++) {
        int idx = bt*NP + valid_idx[v];
        int masked;
        if (is_int)        masked = (mi[idx] != 0);
        else if (is_float) masked = (mf[idx] != 0.0f);
        else               masked = (mb[idx] != 0);
        if (!masked) { if (cnt < KVIS) g_tokv[base+cnt] = v; cnt++; }
    }
}

// ---------------- patchify + patch embed + pos encodings ----------------
__global__ void __launch_bounds__(256) embed_kernel(
    const float* __restrict__ img, const int* __restrict__ valid_idx,
    const float* __restrict__ Wpe, const float* __restrict__ bpe,
    const float* __restrict__ spos)
{
    __shared__ float pix[16][PD];
    __shared__ float wsm[DD][27];
    __shared__ int sm_v[16], sm_t[16], sm_off[16];
    int tid = threadIdx.x;
    int m0 = blockIdx.x * 16;
    if (tid < 16) {
        int m = m0 + tid;
        int b = m / LL;
        int l = m - b*LL;
        int t = l / KVIS;
        int v = g_tokv[m];
        int patch = valid_idx[v];
        int hp = patch / NWP, wp = patch - hp*NWP;
        sm_v[tid] = v; sm_t[tid] = t;
        sm_off[tid] = ((b*TT + t)*HIMG + hp*PS)*WIMG + wp*PS;
    }
    __syncthreads();
    for (int j = tid; j < 16*PD; j += 256) {
        int tok = j / PD, pd = j - tok*PD;
        int ph = pd / PS, pw = pd - ph*PS;
        pix[tok][pd] = img[sm_off[tok] + ph*WIMG + pw];
    }
    float acc[16];
    #pragma unroll
    for (int i = 0; i < 16; i++) acc[i] = 0.f;
    for (int k0 = 0; k0 < PD; k0 += 25) {
        __syncthreads();
        for (int j = tid; j < DD*25; j += 256) {
            int dd = j / 25, kk = j - dd*25;
            wsm[dd][kk] = Wpe[dd*PD + k0 + kk];
        }
        __syncthreads();
        #pragma unroll
        for (int kk = 0; kk < 25; kk++) {
            float w = wsm[tid][kk];
            #pragma unroll
            for (int tok = 0; tok < 16; tok++)
                acc[tok] = fmaf(w, pix[tok][k0+kk], acc[tok]);
        }
    }
    int d = tid;
    float freq = expf((float)(d & ~1) * (-9.210340371976184f / 256.f));
    float pb = bpe[d];
    #pragma unroll
    for (int tok = 0; tok < 16; tok++) {
        float val = (float)sm_t[tok] * freq;
        float pe = (d & 1) ? cosf(val) : sinf(val);
        g_x[(m0+tok)*DD + d] = acc[tok] + pb + spos[sm_v[tok]*DD + d] + pe;
    }
}

// ---------------- one-time prep: weights -> single fp16, layer-major -------
__global__ void prep_weights_kernel(const float* __restrict__ Wqkv, const float* __restrict__ Wo,
                                    const float* __restrict__ W1, const float* __restrict__ W2)
{
    int i = blockIdx.x*blockDim.x + threadIdx.x;
    int layer = i / WLAYER;
    int r = i - layer*WLAYER;
    float v;
    if      (r < WOFS_O) v = Wqkv[layer*196608 + r];
    else if (r < WOFS_1) v = Wo[layer*65536 + r - WOFS_O];
    else if (r < WOFS_2) v = W1[layer*262144 + r - WOFS_1];
    else                 v = W2[layer*262144 + r - WOFS_2];
    g_wh[i] = __float2half_rn(v);
}

// ---------------- x fp32 -> single fp16 (after embed only) ----------------
__global__ void cvt_x_kernel()
{
    int i = blockIdx.x*blockDim.x + threadIdx.x;   // over MM*DD/2
    float2 v = ((const float2*)g_x)[i];
    ((unsigned*)g_xh)[i] = packh(v.x, v.y);
}

// ---------------- fp16 tensor-core GEMM, 3-stage cp.async ring -------------
// C[m,n] = sum_k A[m,k]*W[n,k] + bias[n].  Single-term fp16 A and W.
// OUTMODE: 0 fp32 C; 1 fp16 Ch; 2 fused QKV epilogue.
#define GSTR 24
#define GARR (128*GSTR)
#define GSTAGE (2*GARR)
#define GEMM_SMEM (3*GSTAGE*2)

template<int OUTMODE, int RELU>
__global__ void __launch_bounds__(256,2) gemm_kernel(
    const __half* __restrict__ Ahg,
    const __half* __restrict__ Whg,
    const float* __restrict__ bias,
    float* __restrict__ C, __half* __restrict__ Ch,
    int Ndim, int Kdim)
{
    extern __shared__ __align__(16) char smraw[];
    __half* smb = (__half*)smraw;
    uint32_t smb_u = sptr(smraw);
    int tid = threadIdx.x, lane = tid & 31, wid = tid >> 5;
    int wm = wid >> 1, wn = wid & 1;
    int m0 = blockIdx.x*128, n0 = blockIdx.y*128;

    const __half* srcs[2];
    srcs[0] = Ahg + (size_t)m0*Kdim;
    srcs[1] = Whg + (size_t)n0*Kdim;

    float acc[2][8][4];
    #pragma unroll
    for (int i=0;i<2;i++)
        #pragma unroll
        for (int j=0;j<8;j++)
            #pragma unroll
            for (int q=0;q<4;q++) acc[i][j][q]=0.f;

    int arow = wm*32 + (lane & 15);
    int akoff = (lane >> 4) << 3;
    int brow = wn*64 + ((lane >> 4) << 3) + (lane & 7);
    int bkoff = ((lane >> 3) & 1) << 3;

    #define GEMM_ISSUE(s, k0) do { \
        uint32_t base_ = smb_u + (s)*GSTAGE*2; \
        _Pragma("unroll") \
        for (int it_ = 0; it_ < 2; it_++) { \
            int idx_ = it_*256 + tid; \
            int arr_ = idx_ >> 8, rem_ = idx_ & 255; \
            int row_ = rem_ >> 1, ch_ = rem_ & 1; \
            const void* gp_ = srcs[arr_] + (size_t)row_*Kdim + (k0) + ch_*8; \
            uint32_t dst_ = base_ + (arr_*GARR + row_*GSTR + ch_*8)*2; \
            cp16(dst_, gp_); \
        } \
    } while(0)

    GEMM_ISSUE(0, 0);  CP_COMMIT();
    GEMM_ISSUE(1, 16); CP_COMMIT();

    int NTK = Kdim >> 4;
    for (int t = 0; t < NTK; t++) {
        CP_WAIT1();
        __syncthreads();
        if (t + 2 < NTK) {
            int s = (t+2) % 3;
            GEMM_ISSUE(s, (t+2)*16);
        }
        CP_COMMIT();

        __half* Ah = smb + (t%3)*GSTAGE;
        __half* Wh = Ah + GARR;

        unsigned ah0[4], ah1[4];
        ldsm4(ah0[0],ah0[1],ah0[2],ah0[3], sptr(Ah + arow*GSTR + akoff));
        ldsm4(ah1[0],ah1[1],ah1[2],ah1[3], sptr(Ah + (arow+16)*GSTR + akoff));

        unsigned bf[4][4];
        #pragma unroll
        for (int p = 0; p < 4; p++)
            ldsm4(bf[p][0],bf[p][1],bf[p][2],bf[p][3], sptr(Wh + (brow + p*16)*GSTR + bkoff));
        #pragma unroll
        for (int p = 0; p < 4; p++) {
            mma_f16(acc[0][2*p],   ah0, bf[p][0], bf[p][1]);
            mma_f16(acc[0][2*p+1], ah0, bf[p][2], bf[p][3]);
            mma_f16(acc[1][2*p],   ah1, bf[p][0], bf[p][1]);
            mma_f16(acc[1][2*p+1], ah1, bf[p][2], bf[p][3]);
        }
        __syncthreads();
    }

    // epilogue
    int r0 = lane >> 2;
    int c2 = (lane & 3) << 1;
    #pragma unroll
    for (int ma = 0; ma < 2; ma++) {
        #pragma unroll
        for (int na = 0; na < 8; na++) {
            int col = n0 + wn*64 + na*8 + c2;
            float2 bsv = *(const float2*)(bias + col);
            float v0 = acc[ma][na][0] + bsv.x;
            float v1 = acc[ma][na][1] + bsv.y;
            float v2 = acc[ma][na][2] + bsv.x;
            float v3 = acc[ma][na][3] + bsv.y;
            int row = m0 + wm*32 + ma*16 + r0;
            if (OUTMODE == 2) {
                // fused QKV: seg 0=Q(scaled,single), 1=K(single), 2=V^T(single)
                int seg = col >> 8;
                int h = (col >> 5) & 7;
                int dh = col & 31;
                if (seg == 0) { v0 *= QSCALE; v1 *= QSCALE; v2 *= QSCALE; v3 *= QSCALE; }
                #pragma unroll
                for (int half = 0; half < 2; half++) {
                    int rr = row + half*8;
                    float a0 = half ? v2 : v0;
                    float a1 = half ? v3 : v1;
                    int bb = rr / LL;
                    int l = rr - bb*LL;
                    int bh = bb*8 + h;
                    if (seg < 2) {
                        size_t o = ((size_t)bh*LL + l)*16 + (dh >> 1);
                        ((unsigned*)(seg == 0 ? g_qh : g_kh))[o] = packh(a0, a1);
                    } else {
                        size_t o0 = ((size_t)bh*32 + dh)*LTP + l;
                        size_t o1 = ((size_t)bh*32 + dh + 1)*LTP + l;
                        g_vth[o0] = __float2half_rn(a0);
                        g_vth[o1] = __float2half_rn(a1);
                    }
                }
            } else {
                if (RELU) {
                    v0 = fmaxf(v0,0.f); v1 = fmaxf(v1,0.f);
                    v2 = fmaxf(v2,0.f); v3 = fmaxf(v3,0.f);
                }
                if (OUTMODE == 1) {
                    size_t o = ((size_t)row*Ndim + col) >> 1;
                    ((unsigned*)Ch)[o] = packh(v0, v1);
                    o = ((size_t)(row+8)*Ndim + col) >> 1;
                    ((unsigned*)Ch)[o] = packh(v2, v3);
                } else {
                    *(float2*)(C + (size_t)row*Ndim + col) = make_float2(v0, v1);
                    *(float2*)(C + (size_t)(row+8)*Ndim + col) = make_float2(v2, v3);
                }
            }
        }
    }
}

// ---------------- flash attention, pure fp16 operands, exp2 softmax --------
// QK 1-term (Qh x Kh), PV 1-term (Ph x Vh). Logits in log2 units.
#define AQ_ELEMS (128*40)
#define AKV_ELEMS 4864
#define ATT_SMEM ((AQ_ELEMS + 3*AKV_ELEMS)*2)

__global__ void __launch_bounds__(256,2) attn_kernel(__half* __restrict__ outh)
{
    extern __shared__ __align__(16) char smraw[];
    __half* smb = (__half*)smraw;
    uint32_t smb_u = sptr(smraw);
    __half* Qhs = smb;                 // [128][40]

    int tid = threadIdx.x, lane = tid & 31, wid = tid >> 5;
    int q0 = blockIdx.x * 128;
    int bh = blockIdx.y;
    int b = bh >> 3, h = bh & 7;

    #define ATT_ISSUE(s, k0t) do { \
        uint32_t sb_ = smb_u + (AQ_ELEMS + (s)*AKV_ELEMS)*2; \
        _Pragma("unroll") \
        for (int it_ = 0; it_ < 2; it_++) { \
            int idx_ = it_*256 + tid; \
            if (idx_ < 256) { \
                int r_ = idx_ >> 2, c_ = idx_ & 3; \
                int krow_ = (k0t) + r_; \
                int pred_ = (krow_ < LL); \
                int kc_ = pred_ ? krow_ : 0; \
                const __half* src_ = g_kh + ((size_t)bh*LL + kc_)*32 + c_*8; \
                uint32_t dst_ = sb_ + (r_*40 + c_*8)*2; \
                cp16p(dst_, src_, pred_); \
            } else { \
                int j_ = idx_ - 256; \
                int dd_ = j_ >> 3, c_ = j_ & 7; \
                const __half* src_ = g_vth + ((size_t)bh*32 + dd_)*LTP + (k0t) + c_*8; \
                uint32_t dst_ = sb_ + (2560 + dd_*72 + c_*8)*2; \
                cp16(dst_, src_); \
            } \
        } \
    } while(0)

    // ---- Q copy via cp.async ----
    #pragma unroll
    for (int it = 0; it < 2; it++) {
        int idx = it*256 + tid;
        int r = idx >> 2, c = idx & 3;
        int qrow = q0 + r;
        int pred = (qrow < LL);
        int qc = pred ? qrow : 0;
        const __half* src = g_qh + ((size_t)bh*LL + qc)*32 + c*8;
        uint32_t dst = smb_u + (r*40 + c*8)*2;
        cp16p(dst, src, pred);
    }
    ATT_ISSUE(0, 0);  CP_COMMIT();
    ATT_ISSUE(1, 64); CP_COMMIT();

    int arow = wid*16 + (lane & 15);
    int akoff = (lane >> 4) << 3;
    int brow = ((lane >> 4) << 3) + (lane & 7);
    int bkoff = ((lane >> 3) & 1) << 3;
    int c2 = (lane & 3) << 1;

    float sO[4][4];
    #pragma unroll
    for (int i=0;i<4;i++)
        #pragma unroll
        for (int j=0;j<4;j++) sO[i][j]=0.f;
    float mrow[2] = {-1e30f, -1e30f};
    float lrow[2] = {0.f, 0.f};

    for (int kt = 0; kt < 34; kt++) {
        int k0t = kt*64;
        CP_WAIT1();
        __syncthreads();
        if (kt + 2 < 34) {
            int s = (kt+2) % 3;
            ATT_ISSUE(s, (kt+2)*64);
        }
        CP_COMMIT();

        __half* Khs = smb + AQ_ELEMS + (kt%3)*AKV_ELEMS;
        __half* Vhs = Khs + 2560;

        // ---- S = Q K^T (1-term) ----
        float s[8][4];
        #pragma unroll
        for (int i=0;i<8;i++)
            #pragma unroll
            for (int j=0;j<4;j++) s[i][j]=0.f;
        #pragma unroll
        for (int ks = 0; ks < 2; ks++) {
            unsigned ah[4];
            ldsm4(ah[0],ah[1],ah[2],ah[3], sptr(Qhs + arow*40 + ks*16 + akoff));
            unsigned kb[4][4];
            #pragma unroll
            for (int p = 0; p < 4; p++)
                ldsm4(kb[p][0],kb[p][1],kb[p][2],kb[p][3], sptr(Khs + (brow + p*16)*40 + ks*16 + bkoff));
            #pragma unroll
            for (int p = 0; p < 4; p++) {
                mma_f16(s[2*p],   ah, kb[p][0], kb[p][1]);
                mma_f16(s[2*p+1], ah, kb[p][2], kb[p][3]);
            }
        }

        // ---- online softmax in exp2 domain (log2e pre-folded into Q) ----
        int tail = (k0t + 64 > LL);
        float fac[2];
        #pragma unroll
        for (int hf = 0; hf < 2; hf++) {
            float vmax = -1e30f;
            #pragma unroll
            for (int na = 0; na < 8; na++) {
                float v0 = s[na][2*hf];
                float v1 = s[na][2*hf+1];
                if (tail) {
                    if (k0t + na*8 + c2     >= LL) v0 = -1e30f;
                    if (k0t + na*8 + c2 + 1 >= LL) v1 = -1e30f;
                }
                s[na][2*hf] = v0; s[na][2*hf+1] = v1;
                vmax = fmaxf(vmax, fmaxf(v0, v1));
            }
            vmax = fmaxf(vmax, __shfl_xor_sync(0xffffffffu, vmax, 1));
            vmax = fmaxf(vmax, __shfl_xor_sync(0xffffffffu, vmax, 2));
            float mnew = fmaxf(mrow[hf], vmax);
            fac[hf] = exp2f(mrow[hf] - mnew);
            mrow[hf] = mnew;
            float ps = 0.f;
            #pragma unroll
            for (int na = 0; na < 8; na++) {
                float p0 = exp2f(s[na][2*hf]   - mnew);
                float p1 = exp2f(s[na][2*hf+1] - mnew);
                s[na][2*hf] = p0; s[na][2*hf+1] = p1;
                ps += p0 + p1;
            }
            ps += __shfl_xor_sync(0xffffffffu, ps, 1);
            ps += __shfl_xor_sync(0xffffffffu, ps, 2);
            lrow[hf] = lrow[hf]*fac[hf] + ps;
        }

        // ---- pack P fragments ----
        unsigned pah[4][4];
        #pragma unroll
        for (int ks = 0; ks < 4; ks++) {
            pah[ks][0] = packh(s[2*ks][0],   s[2*ks][1]);
            pah[ks][1] = packh(s[2*ks][2],   s[2*ks][3]);
            pah[ks][2] = packh(s[2*ks+1][0], s[2*ks+1][1]);
            pah[ks][3] = packh(s[2*ks+1][2], s[2*ks+1][3]);
        }

        // ---- rescale O ----
        #pragma unroll
        for (int na = 0; na < 4; na++) {
            sO[na][0] *= fac[0]; sO[na][1] *= fac[0];
            sO[na][2] *= fac[1]; sO[na][3] *= fac[1];
        }

        // ---- O += P V ----
        #pragma unroll
        for (int ks = 0; ks < 4; ks++) {
            unsigned vb[2][4];
            #pragma unroll
            for (int p = 0; p < 2; p++)
                ldsm4(vb[p][0],vb[p][1],vb[p][2],vb[p][3], sptr(Vhs + (brow + p*16)*72 + ks*16 + bkoff));
            #pragma unroll
            for (int p = 0; p < 2; p++) {
                mma_f16(sO[2*p],   pah[ks], vb[p][0], vb[p][1]);
                mma_f16(sO[2*p+1], pah[ks], vb[p][2], vb[p][3]);
            }
        }
    }

    // ---- normalize + store single fp16 ----
    int r0 = lane >> 2;
    float inv0 = 1.f / lrow[0];
    float inv1 = 1.f / lrow[1];
    #pragma unroll
    for (int na = 0; na < 4; na++) {
        int col = h*DH + na*8 + c2;
        int qrow = q0 + wid*16 + r0;
        if (qrow < LL) {
            size_t o = (((size_t)(b*LL + qrow))*DD + col) >> 1;
            ((unsigned*)outh)[o] = packh(sO[na][0]*inv0, sO[na][1]*inv0);
        }
        if (qrow + 8 < LL) {
            size_t o = (((size_t)(b*LL + qrow + 8))*DD + col) >> 1;
            ((unsigned*)outh)[o] = packh(sO[na][2]*inv1, sO[na][3]*inv1);
        }
    }
}

// ---------------- residual add + LayerNorm (warp/row) + optional fp16 out --
__global__ void __launch_bounds__(256) add_ln_kernel(
    const float* __restrict__ x, const float* __restrict__ y,
    const float* __restrict__ gam, const float* __restrict__ bet,
    float* __restrict__ out, __half* __restrict__ oh,
    int doadd)
{
    int warp = threadIdx.x >> 5, lane = threadIdx.x & 31;
    int row = blockIdx.x*8 + warp;
    const float* xr = x + (size_t)row*DD + lane*8;
    float v[8];
    float4 va = *(const float4*)(xr);
    float4 vb = *(const float4*)(xr + 4);
    v[0]=va.x; v[1]=va.y; v[2]=va.z; v[3]=va.w;
    v[4]=vb.x; v[5]=vb.y; v[6]=vb.z; v[7]=vb.w;
    if (doadd) {
        const float* yr = y + (size_t)row*DD + lane*8;
        float4 ya = *(const float4*)(yr);
        float4 yb = *(const float4*)(yr + 4);
        v[0]+=ya.x; v[1]+=ya.y; v[2]+=ya.z; v[3]+=ya.w;
        v[4]+=yb.x; v[5]+=yb.y; v[6]+=yb.z; v[7]+=yb.w;
    }
    float s = 0.f;
    #pragma unroll
    for (int i=0;i<8;i++) s += v[i];
    #pragma unroll
    for (int off=16; off; off>>=1) s += __shfl_xor_sync(0xffffffffu, s, off);
    float mean = s * (1.f/DD);
    float s2 = 0.f;
    #pragma unroll
    for (int i=0;i<8;i++) { v[i] -= mean; s2 += v[i]*v[i]; }
    #pragma unroll
    for (int off=16; off; off>>=1) s2 += __shfl_xor_sync(0xffffffffu, s2, off);
    float rstd = rsqrtf(s2 * (1.f/DD) + 1e-5f);
    const float* gp = gam + lane*8;
    const float* bp = bet + lane*8;
    float4 ga = *(const float4*)(gp);
    float4 gb = *(const float4*)(gp+4);
    float4 ba = *(const float4*)(bp);
    float4 bb = *(const float4*)(bp+4);
    float g[8] = {ga.x,ga.y,ga.z,ga.w,gb.x,gb.y,gb.z,gb.w};
    float be[8] = {ba.x,ba.y,ba.z,ba.w,bb.x,bb.y,bb.z,bb.w};
    float o[8];
    #pragma unroll
    for (int i=0;i<8;i++) o[i] = v[i]*rstd*g[i] + be[i];
    float* op = out + (size_t)row*DD + lane*8;
    *(float4*)(op)   = make_float4(o[0],o[1],o[2],o[3]);
    *(float4*)(op+4) = make_float4(o[4],o[5],o[6],o[7]);
    if (oh) {
        unsigned hw[4];
        hw[0] = packh(o[0],o[1]);
        hw[1] = packh(o[2],o[3]);
        hw[2] = packh(o[4],o[5]);
        hw[3] = packh(o[6],o[7]);
        size_t ob = ((size_t)row*DD + lane*8) >> 1;
        *(uint4*)((unsigned*)oh + ob) = make_uint4(hw[0],hw[1],hw[2],hw[3]);
    }
}

// ---------------- launch ----------------
extern "C" void kernel_launch(void* const* d_in, const int* in_sizes, int n_in,
                              void* d_out, int out_size)
{
    const float* x_img          = (const float*)d_in[0];
    const void*  pmask          = (const void*)d_in[1];
    const int*   valid_idx      = (const int*)d_in[2];
    const float* pe_w           = (const float*)d_in[3];
    const float* pe_b           = (const float*)d_in[4];
    const float* spos           = (const float*)d_in[5];
    const float* Wqkv           = (const float*)d_in[6];
    const float* bqkv           = (const float*)d_in[7];
    const float* Wo             = (const float*)d_in[8];
    const float* bo             = (const float*)d_in[9];
    const float* ln1s           = (const float*)d_in[10];
    const float* ln1b           = (const float*)d_in[11];
    const float* W1             = (const float*)d_in[12];
    const float* b1             = (const float*)d_in[13];
    const float* W2             = (const float*)d_in[14];
    const float* b2             = (const float*)d_in[15];
    const float* ln2s           = (const float*)d_in[16];
    const float* ln2b           = (const float*)d_in[17];
    const float* nfs            = (const float*)d_in[18];
    const float* nfb            = (const float*)d_in[19];
    float* out = (float*)d_out;

    float *px, *py;
    __half *pxh, *path, *pffh, *pwh;
    cudaGetSymbolAddress((void**)&px,   g_x);
    cudaGetSymbolAddress((void**)&py,   g_y);
    cudaGetSymbolAddress((void**)&pxh,  g_xh);
    cudaGetSymbolAddress((void**)&path, g_atth);
    cudaGetSymbolAddress((void**)&pffh, g_ffh);
    cudaGetSymbolAddress((void**)&pwh,  g_wh);

    cudaFuncSetAttribute(attn_kernel, cudaFuncAttributeMaxDynamicSharedMemorySize, ATT_SMEM);
    cudaFuncSetAttribute(gemm_kernel<2,0>, cudaFuncAttributeMaxDynamicSharedMemorySize, GEMM_SMEM);
    cudaFuncSetAttribute(gemm_kernel<0,0>, cudaFuncAttributeMaxDynamicSharedMemorySize, GEMM_SMEM);
    cudaFuncSetAttribute(gemm_kernel<1,1>, cudaFuncAttributeMaxDynamicSharedMemorySize, GEMM_SMEM);

    prep_weights_kernel<<<WTOTAL/256, 256>>>(Wqkv, Wo, W1, W2);
    build_vis_kernel<<<(BB*TT+255)/256, 256>>>(pmask, valid_idx);
    embed_kernel<<<MM/16, 256>>>(x_img, valid_idx, pe_w, pe_b, spos);
    cvt_x_kernel<<<MM*DD/512, 256>>>();

    for (int i = 0; i < NLAYERS; i++) {
        const __half* wh = pwh + (size_t)i*WLAYER;
        // QKV GEMM (fp16 x) with fused Q/K/V^T epilogue
        gemm_kernel<2,0><<<dim3(MM/128, 6), 256, GEMM_SMEM>>>(
            pxh, wh + WOFS_QKV, bqkv + i*768,
            nullptr, nullptr, 768, 256);
        attn_kernel<<<dim3(17, BB*NHEAD), 256, ATT_SMEM>>>(path);
        // Wo GEMM
        gemm_kernel<0,0><<<dim3(MM/128, 2), 256, GEMM_SMEM>>>(
            path, wh + WOFS_O, bo + i*256,
            py, nullptr, 256, 256);
        add_ln_kernel<<<MM/8, 256>>>(px, py, ln1s + i*DD, ln1b + i*DD, px, pxh, 1);
        // FF1 GEMM -> relu -> fp16
        gemm_kernel<1,1><<<dim3(MM/128, 8), 256, GEMM_SMEM>>>(
            pxh, wh + WOFS_1, b1 + i*DFF,
            nullptr, pffh, 1024, 256);
        // FF2 GEMM
        gemm_kernel<0,0><<<dim3(MM/128, 2), 256, GEMM_SMEM>>>(
            pffh, wh + WOFS_2, b2 + i*256,
            py, nullptr, 256, 1024);
        add_ln_kernel<<<MM/8, 256>>>(px, py, ln2s + i*DD, ln2b + i*DD, px, pxh, 1);
    }
    add_ln_kernel<<<MM/8, 256>>>(px, px, nfs, nfb, out, nullptr, 0);
}

// round 17
// speedup vs baseline: 1.7630x; 1.0316x over previous
#include <cuda_runtime.h>
#include <cuda_fp16.h>
#include <math.h>
#include <stdint.h>

#define BB 8
#define TT 90
#define HIMG 290
#define WIMG 180
#define PS 10
#define NWP 18
#define NP 522
#define PD 100
#define NV 94
#define KVIS 24
#define LL 2160
#define DD 256
#define NHEAD 8
#define DH 32
#define NLAYERS 6
#define DFF 1024
#define MM (BB*LL)   /* 17280 */
#define LTP 2176     /* LL padded to 68*32 */
#define QSCALE (0.17677669529663687f * 1.4426950408889634f)  /* fold log2e */

// per-layer weight segment offsets (elements), layer stride
#define WOFS_QKV 0
#define WOFS_O   196608
#define WOFS_1   262144
#define WOFS_2   524288
#define WLAYER   786432
#define WTOTAL   (6*WLAYER)

// ---------------- scratch (no cudaMalloc allowed) ----------------
__device__ float g_x[MM*DD];
__device__ float g_y[MM*DD];
__device__ __half g_xh[MM*DD];                     // x single fp16
__device__ __half g_atth[MM*DD];                   // attention out, single fp16
__device__ __half g_ffh[MM*DFF];                   // FF1 out, single fp16
__device__ __half g_qh[BB*NHEAD*LL*DH];            // Q single fp16 (pre-scaled)
__device__ __half g_kh[BB*NHEAD*LL*DH];            // K single fp16
__device__ __half g_vth[BB*NHEAD*DH*LTP];          // V single fp16, transposed
__device__ __half g_wh[WTOTAL];                    // weights single fp16
__device__ int   g_tokv[MM];

// ---------------- helpers ----------------
__device__ __forceinline__ unsigned sptr(const void* p) {
    return (unsigned)__cvta_generic_to_shared(p);
}
__device__ __forceinline__ void ldsm4(unsigned &r0, unsigned &r1, unsigned &r2, unsigned &r3, unsigned addr) {
    asm volatile("ldmatrix.sync.aligned.m8n8.x4.shared.b16 {%0,%1,%2,%3}, [%4];"
                 : "=r"(r0), "=r"(r1), "=r"(r2), "=r"(r3) : "r"(addr));
}
__device__ __forceinline__ void mma_f16(float* c, const unsigned* a, unsigned b0, unsigned b1) {
    asm volatile("mma.sync.aligned.m16n8k16.row.col.f32.f16.f16.f32 "
                 "{%0,%1,%2,%3}, {%4,%5,%6,%7}, {%8,%9}, {%0,%1,%2,%3};"
                 : "+f"(c[0]), "+f"(c[1]), "+f"(c[2]), "+f"(c[3])
                 : "r"(a[0]), "r"(a[1]), "r"(a[2]), "r"(a[3]), "r"(b0), "r"(b1));
}
// pack two f32 as fp16 pair
__device__ __forceinline__ unsigned packh(float x0, float x1) {
    __half h0 = __float2half_rn(x0), h1 = __float2half_rn(x1);
    return (unsigned)__half_as_ushort(h0) | ((unsigned)__half_as_ushort(h1) << 16);
}
// fp16x2 exp2 (single MUFU for two values)
__device__ __forceinline__ unsigned hex2(unsigned a) {
    unsigned d; asm("ex2.approx.f16x2 %0, %1;" : "=r"(d) : "r"(a)); return d;
}
__device__ __forceinline__ unsigned hadd2u(unsigned a, unsigned b) {
    unsigned d; asm("add.f16x2 %0, %1, %2;" : "=r"(d) : "r"(a), "r"(b)); return d;
}
__device__ __forceinline__ float2 h22f2(unsigned a) {
    __half2 h = *(__half2*)&a; return __half22float2(h);
}
__device__ __forceinline__ void cp16(uint32_t dst, const void* src) {
    asm volatile("cp.async.cg.shared.global [%0], [%1], 16;" :: "r"(dst), "l"(src) : "memory");
}
__device__ __forceinline__ void cp16p(uint32_t dst, const void* src, int pred) {
    int sz = pred ? 16 : 0;
    asm volatile("cp.async.cg.shared.global [%0], [%1], 16, %2;" :: "r"(dst), "l"(src), "r"(sz) : "memory");
}
#define CP_COMMIT() asm volatile("cp.async.commit_group;" ::: "memory")
#define CP_WAIT1()  asm volatile("cp.async.wait_group 1;" ::: "memory")

// ---------------- token list ----------------
__global__ void build_vis_kernel(const void* __restrict__ mask_raw,
                                 const int* __restrict__ valid_idx)
{
    int bt = blockIdx.x*blockDim.x + threadIdx.x;
    if (bt >= BB*TT) return;
    const int*   mi = (const int*)mask_raw;
    const float* mf = (const float*)mask_raw;
    const unsigned char* mb = (const unsigned char*)mask_raw;
    int is_int = 1;
    for (int j = 0; j < NP; j++) { int w = mi[j]; if (w != 0 && w != 1) { is_int = 0; break; } }
    int is_float = 0;
    if (!is_int) {
        is_float = 1;
        for (int j = 0; j < NP; j++) { float w = mf[j]; if (w != 0.0f && w != 1.0f) { is_float = 0; break; } }
    }
    int base = bt*KVIS, cnt = 0;
    for (int v = 0; v < NV; v++) {
        int idx = bt*NP + valid_idx[v];
        int masked;
        if (is_int)        masked = (mi[idx] != 0);
        else if (is_float) masked = (mf[idx] != 0.0f);
        else               masked = (mb[idx] != 0);
        if (!masked) { if (cnt < KVIS) g_tokv[base+cnt] = v; cnt++; }
    }
}

// ---------------- patchify + patch embed + pos encodings ----------------
__global__ void __launch_bounds__(256) embed_kernel(
    const float* __restrict__ img, const int* __restrict__ valid_idx,
    const float* __restrict__ Wpe, const float* __restrict__ bpe,
    const float* __restrict__ spos)
{
    __shared__ float pix[16][PD];
    __shared__ float wsm[DD][27];
    __shared__ int sm_v[16], sm_t[16], sm_off[16];
    int tid = threadIdx.x;
    int m0 = blockIdx.x * 16;
    if (tid < 16) {
        int m = m0 + tid;
        int b = m / LL;
        int l = m - b*LL;
        int t = l / KVIS;
        int v = g_tokv[m];
        int patch = valid_idx[v];
        int hp = patch / NWP, wp = patch - hp*NWP;
        sm_v[tid] = v; sm_t[tid] = t;
        sm_off[tid] = ((b*TT + t)*HIMG + hp*PS)*WIMG + wp*PS;
    }
    __syncthreads();
    for (int j = tid; j < 16*PD; j += 256) {
        int tok = j / PD, pd = j - tok*PD;
        int ph = pd / PS, pw = pd - ph*PS;
        pix[tok][pd] = img[sm_off[tok] + ph*WIMG + pw];
    }
    float acc[16];
    #pragma unroll
    for (int i = 0; i < 16; i++) acc[i] = 0.f;
    for (int k0 = 0; k0 < PD; k0 += 25) {
        __syncthreads();
        for (int j = tid; j < DD*25; j += 256) {
            int dd = j / 25, kk = j - dd*25;
            wsm[dd][kk] = Wpe[dd*PD + k0 + kk];
        }
        __syncthreads();
        #pragma unroll
        for (int kk = 0; kk < 25; kk++) {
            float w = wsm[tid][kk];
            #pragma unroll
            for (int tok = 0; tok < 16; tok++)
                acc[tok] = fmaf(w, pix[tok][k0+kk], acc[tok]);
        }
    }
    int d = tid;
    float freq = expf((float)(d & ~1) * (-9.210340371976184f / 256.f));
    float pb = bpe[d];
    #pragma unroll
    for (int tok = 0; tok < 16; tok++) {
        float val = (float)sm_t[tok] * freq;
        float pe = (d & 1) ? cosf(val) : sinf(val);
        g_x[(m0+tok)*DD + d] = acc[tok] + pb + spos[sm_v[tok]*DD + d] + pe;
    }
}

// ---------------- one-time prep: weights -> single fp16, layer-major -------
__global__ void prep_weights_kernel(const float* __restrict__ Wqkv, const float* __restrict__ Wo,
                                    const float* __restrict__ W1, const float* __restrict__ W2)
{
    int i = blockIdx.x*blockDim.x + threadIdx.x;
    int layer = i / WLAYER;
    int r = i - layer*WLAYER;
    float v;
    if      (r < WOFS_O) v = Wqkv[layer*196608 + r];
    else if (r < WOFS_1) v = Wo[layer*65536 + r - WOFS_O];
    else if (r < WOFS_2) v = W1[layer*262144 + r - WOFS_1];
    else                 v = W2[layer*262144 + r - WOFS_2];
    g_wh[i] = __float2half_rn(v);
}

// ---------------- x fp32 -> single fp16 (after embed only) ----------------
__global__ void cvt_x_kernel()
{
    int i = blockIdx.x*blockDim.x + threadIdx.x;   // over MM*DD/2
    float2 v = ((const float2*)g_x)[i];
    ((unsigned*)g_xh)[i] = packh(v.x, v.y);
}

// ---------------- fp16 tensor-core GEMM, BK=32, 3-stage cp.async ring ------
// C[m,n] = sum_k A[m,k]*W[n,k] + bias[n].  Single-term fp16 A and W.
// OUTMODE: 0 fp32 C; 1 fp16 Ch; 2 fused QKV epilogue.
#define GSTR 40
#define GARR (128*GSTR)
#define GSTAGE (2*GARR)
#define GEMM_SMEM (3*GSTAGE*2)

template<int OUTMODE, int RELU>
__global__ void __launch_bounds__(256,2) gemm_kernel(
    const __half* __restrict__ Ahg,
    const __half* __restrict__ Whg,
    const float* __restrict__ bias,
    float* __restrict__ C, __half* __restrict__ Ch,
    int Ndim, int Kdim)
{
    extern __shared__ __align__(16) char smraw[];
    __half* smb = (__half*)smraw;
    uint32_t smb_u = sptr(smraw);
    int tid = threadIdx.x, lane = tid & 31, wid = tid >> 5;
    int wm = wid >> 1, wn = wid & 1;
    int m0 = blockIdx.x*128, n0 = blockIdx.y*128;

    const __half* srcs[2];
    srcs[0] = Ahg + (size_t)m0*Kdim;
    srcs[1] = Whg + (size_t)n0*Kdim;

    float acc[2][8][4];
    #pragma unroll
    for (int i=0;i<2;i++)
        #pragma unroll
        for (int j=0;j<8;j++)
            #pragma unroll
            for (int q=0;q<4;q++) acc[i][j][q]=0.f;

    int arow = wm*32 + (lane & 15);
    int akoff = (lane >> 4) << 3;
    int brow = wn*64 + ((lane >> 4) << 3) + (lane & 7);
    int bkoff = ((lane >> 3) & 1) << 3;

    // stage loader: 2 arrays x 128 rows x 4 chunks (16B) = 1024 cp16
    #define GEMM_ISSUE(s, k0) do { \
        uint32_t base_ = smb_u + (s)*GSTAGE*2; \
        _Pragma("unroll") \
        for (int it_ = 0; it_ < 4; it_++) { \
            int idx_ = it_*256 + tid; \
            int arr_ = idx_ >> 9, rem_ = idx_ & 511; \
            int row_ = rem_ >> 2, ch_ = rem_ & 3; \
            const void* gp_ = srcs[arr_] + (size_t)row_*Kdim + (k0) + ch_*8; \
            uint32_t dst_ = base_ + (arr_*GARR + row_*GSTR + ch_*8)*2; \
            cp16(dst_, gp_); \
        } \
    } while(0)

    GEMM_ISSUE(0, 0);  CP_COMMIT();
    GEMM_ISSUE(1, 32); CP_COMMIT();

    int NTK = Kdim >> 5;
    for (int t = 0; t < NTK; t++) {
        CP_WAIT1();
        __syncthreads();
        if (t + 2 < NTK) {
            int s = (t+2) % 3;
            GEMM_ISSUE(s, (t+2)*32);
        }
        CP_COMMIT();

        __half* Ah = smb + (t%3)*GSTAGE;
        __half* Wh = Ah + GARR;

        #pragma unroll
        for (int ks = 0; ks < 2; ks++) {
            unsigned ah0[4], ah1[4];
            ldsm4(ah0[0],ah0[1],ah0[2],ah0[3], sptr(Ah + arow*GSTR + ks*16 + akoff));
            ldsm4(ah1[0],ah1[1],ah1[2],ah1[3], sptr(Ah + (arow+16)*GSTR + ks*16 + akoff));
            unsigned bf[4][4];
            #pragma unroll
            for (int p = 0; p < 4; p++)
                ldsm4(bf[p][0],bf[p][1],bf[p][2],bf[p][3], sptr(Wh + (brow + p*16)*GSTR + ks*16 + bkoff));
            #pragma unroll
            for (int p = 0; p < 4; p++) {
                mma_f16(acc[0][2*p],   ah0, bf[p][0], bf[p][1]);
                mma_f16(acc[0][2*p+1], ah0, bf[p][2], bf[p][3]);
                mma_f16(acc[1][2*p],   ah1, bf[p][0], bf[p][1]);
                mma_f16(acc[1][2*p+1], ah1, bf[p][2], bf[p][3]);
            }
        }
        __syncthreads();
    }

    // epilogue
    int r0 = lane >> 2;
    int c2 = (lane & 3) << 1;
    #pragma unroll
    for (int ma = 0; ma < 2; ma++) {
        #pragma unroll
        for (int na = 0; na < 8; na++) {
            int col = n0 + wn*64 + na*8 + c2;
            float2 bsv = *(const float2*)(bias + col);
            float v0 = acc[ma][na][0] + bsv.x;
            float v1 = acc[ma][na][1] + bsv.y;
            float v2 = acc[ma][na][2] + bsv.x;
            float v3 = acc[ma][na][3] + bsv.y;
            int row = m0 + wm*32 + ma*16 + r0;
            if (OUTMODE == 2) {
                // fused QKV: seg 0=Q(scaled,single), 1=K(single), 2=V^T(single)
                int seg = col >> 8;
                int h = (col >> 5) & 7;
                int dh = col & 31;
                if (seg == 0) { v0 *= QSCALE; v1 *= QSCALE; v2 *= QSCALE; v3 *= QSCALE; }
                #pragma unroll
                for (int half = 0; half < 2; half++) {
                    int rr = row + half*8;
                    float a0 = half ? v2 : v0;
                    float a1 = half ? v3 : v1;
                    int bb = rr / LL;
                    int l = rr - bb*LL;
                    int bh = bb*8 + h;
                    if (seg < 2) {
                        size_t o = ((size_t)bh*LL + l)*16 + (dh >> 1);
                        ((unsigned*)(seg == 0 ? g_qh : g_kh))[o] = packh(a0, a1);
                    } else {
                        size_t o0 = ((size_t)bh*32 + dh)*LTP + l;
                        size_t o1 = ((size_t)bh*32 + dh + 1)*LTP + l;
                        g_vth[o0] = __float2half_rn(a0);
                        g_vth[o1] = __float2half_rn(a1);
                    }
                }
            } else {
                if (RELU) {
                    v0 = fmaxf(v0,0.f); v1 = fmaxf(v1,0.f);
                    v2 = fmaxf(v2,0.f); v3 = fmaxf(v3,0.f);
                }
                if (OUTMODE == 1) {
                    size_t o = ((size_t)row*Ndim + col) >> 1;
                    ((unsigned*)Ch)[o] = packh(v0, v1);
                    o = ((size_t)(row+8)*Ndim + col) >> 1;
                    ((unsigned*)Ch)[o] = packh(v2, v3);
                } else {
                    *(float2*)(C + (size_t)row*Ndim + col) = make_float2(v0, v1);
                    *(float2*)(C + (size_t)(row+8)*Ndim + col) = make_float2(v2, v3);
                }
            }
        }
    }
}

// ---------------- flash attention, pure fp16, f16x2 exp2 softmax -----------
// QK 1-term (Qh x Kh), PV 1-term (Ph x Vh). Logits in log2 units.
#define AQ_ELEMS (128*40)
#define AKV_ELEMS 4864
#define ATT_SMEM ((AQ_ELEMS + 3*AKV_ELEMS)*2)

__global__ void __launch_bounds__(256,2) attn_kernel(__half* __restrict__ outh)
{
    extern __shared__ __align__(16) char smraw[];
    __half* smb = (__half*)smraw;
    uint32_t smb_u = sptr(smraw);
    __half* Qhs = smb;                 // [128][40]

    int tid = threadIdx.x, lane = tid & 31, wid = tid >> 5;
    int q0 = blockIdx.x * 128;
    int bh = blockIdx.y;
    int b = bh >> 3, h = bh & 7;

    #define ATT_ISSUE(s, k0t) do { \
        uint32_t sb_ = smb_u + (AQ_ELEMS + (s)*AKV_ELEMS)*2; \
        _Pragma("unroll") \
        for (int it_ = 0; it_ < 2; it_++) { \
            int idx_ = it_*256 + tid; \
            if (idx_ < 256) { \
                int r_ = idx_ >> 2, c_ = idx_ & 3; \
                int krow_ = (k0t) + r_; \
                int pred_ = (krow_ < LL); \
                int kc_ = pred_ ? krow_ : 0; \
                const __half* src_ = g_kh + ((size_t)bh*LL + kc_)*32 + c_*8; \
                uint32_t dst_ = sb_ + (r_*40 + c_*8)*2; \
                cp16p(dst_, src_, pred_); \
            } else { \
                int j_ = idx_ - 256; \
                int dd_ = j_ >> 3, c_ = j_ & 7; \
                const __half* src_ = g_vth + ((size_t)bh*32 + dd_)*LTP + (k0t) + c_*8; \
                uint32_t dst_ = sb_ + (2560 + dd_*72 + c_*8)*2; \
                cp16(dst_, src_); \
            } \
        } \
    } while(0)

    // ---- Q copy via cp.async ----
    #pragma unroll
    for (int it = 0; it < 2; it++) {
        int idx = it*256 + tid;
        int r = idx >> 2, c = idx & 3;
        int qrow = q0 + r;
        int pred = (qrow < LL);
        int qc = pred ? qrow : 0;
        const __half* src = g_qh + ((size_t)bh*LL + qc)*32 + c*8;
        uint32_t dst = smb_u + (r*40 + c*8)*2;
        cp16p(dst, src, pred);
    }
    ATT_ISSUE(0, 0);  CP_COMMIT();
    ATT_ISSUE(1, 64); CP_COMMIT();

    int arow = wid*16 + (lane & 15);
    int akoff = (lane >> 4) << 3;
    int brow = ((lane >> 4) << 3) + (lane & 7);
    int bkoff = ((lane >> 3) & 1) << 3;
    int c2 = (lane & 3) << 1;

    float sO[4][4];
    #pragma unroll
    for (int i=0;i<4;i++)
        #pragma unroll
        for (int j=0;j<4;j++) sO[i][j]=0.f;
    float mrow[2] = {-1e30f, -1e30f};
    float lrow[2] = {0.f, 0.f};

    for (int kt = 0; kt < 34; kt++) {
        int k0t = kt*64;
        CP_WAIT1();
        __syncthreads();
        if (kt + 2 < 34) {
            int s = (kt+2) % 3;
            ATT_ISSUE(s, (kt+2)*64);
        }
        CP_COMMIT();

        __half* Khs = smb + AQ_ELEMS + (kt%3)*AKV_ELEMS;
        __half* Vhs = Khs + 2560;

        // ---- S = Q K^T (1-term) ----
        float s[8][4];
        #pragma unroll
        for (int i=0;i<8;i++)
            #pragma unroll
            for (int j=0;j<4;j++) s[i][j]=0.f;
        #pragma unroll
        for (int ks = 0; ks < 2; ks++) {
            unsigned ah[4];
            ldsm4(ah[0],ah[1],ah[2],ah[3], sptr(Qhs + arow*40 + ks*16 + akoff));
            unsigned kb[4][4];
            #pragma unroll
            for (int p = 0; p < 4; p++)
                ldsm4(kb[p][0],kb[p][1],kb[p][2],kb[p][3], sptr(Khs + (brow + p*16)*40 + ks*16 + bkoff));
            #pragma unroll
            for (int p = 0; p < 4; p++) {
                mma_f16(s[2*p],   ah, kb[p][0], kb[p][1]);
                mma_f16(s[2*p+1], ah, kb[p][2], kb[p][3]);
            }
        }

        // ---- online softmax (exp2 domain; fp16x2 exp) ----
        int tail = (k0t + 64 > LL);
        float fac[2];
        unsigned p2[2][8];
        #pragma unroll
        for (int hf = 0; hf < 2; hf++) {
            float vmax = -1e30f;
            #pragma unroll
            for (int na = 0; na < 8; na++) {
                float v0 = s[na][2*hf];
                float v1 = s[na][2*hf+1];
                if (tail) {
                    if (k0t + na*8 + c2     >= LL) v0 = -1e30f;
                    if (k0t + na*8 + c2 + 1 >= LL) v1 = -1e30f;
                }
                s[na][2*hf] = v0; s[na][2*hf+1] = v1;
                vmax = fmaxf(vmax, fmaxf(v0, v1));
            }
            vmax = fmaxf(vmax, __shfl_xor_sync(0xffffffffu, vmax, 1));
            vmax = fmaxf(vmax, __shfl_xor_sync(0xffffffffu, vmax, 2));
            float mnew = fmaxf(mrow[hf], vmax);
            fac[hf] = exp2f(mrow[hf] - mnew);
            mrow[hf] = mnew;
            #pragma unroll
            for (int na = 0; na < 8; na++) {
                unsigned t = packh(s[na][2*hf] - mnew, s[na][2*hf+1] - mnew);
                p2[hf][na] = hex2(t);
            }
            // sum: one fp16 level, then fp32
            unsigned t0 = hadd2u(p2[hf][0], p2[hf][1]);
            unsigned t1 = hadd2u(p2[hf][2], p2[hf][3]);
            unsigned t2 = hadd2u(p2[hf][4], p2[hf][5]);
            unsigned t3 = hadd2u(p2[hf][6], p2[hf][7]);
            float2 f0 = h22f2(t0), f1 = h22f2(t1), f2 = h22f2(t2), f3 = h22f2(t3);
            float ps = ((f0.x + f0.y) + (f1.x + f1.y)) + ((f2.x + f2.y) + (f3.x + f3.y));
            ps += __shfl_xor_sync(0xffffffffu, ps, 1);
            ps += __shfl_xor_sync(0xffffffffu, ps, 2);
            lrow[hf] = lrow[hf]*fac[hf] + ps;
        }

        // ---- P fragments come directly from p2 ----
        unsigned pah[4][4];
        #pragma unroll
        for (int ks = 0; ks < 4; ks++) {
            pah[ks][0] = p2[0][2*ks];
            pah[ks][1] = p2[1][2*ks];
            pah[ks][2] = p2[0][2*ks+1];
            pah[ks][3] = p2[1][2*ks+1];
        }

        // ---- rescale O ----
        #pragma unroll
        for (int na = 0; na < 4; na++) {
            sO[na][0] *= fac[0]; sO[na][1] *= fac[0];
            sO[na][2] *= fac[1]; sO[na][3] *= fac[1];
        }

        // ---- O += P V ----
        #pragma unroll
        for (int ks = 0; ks < 4; ks++) {
            unsigned vb[2][4];
            #pragma unroll
            for (int p = 0; p < 2; p++)
                ldsm4(vb[p][0],vb[p][1],vb[p][2],vb[p][3], sptr(Vhs + (brow + p*16)*72 + ks*16 + bkoff));
            #pragma unroll
            for (int p = 0; p < 2; p++) {
                mma_f16(sO[2*p],   pah[ks], vb[p][0], vb[p][1]);
                mma_f16(sO[2*p+1], pah[ks], vb[p][2], vb[p][3]);
            }
        }
    }

    // ---- normalize + store single fp16 ----
    int r0 = lane >> 2;
    float inv0 = 1.f / lrow[0];
    float inv1 = 1.f / lrow[1];
    #pragma unroll
    for (int na = 0; na < 4; na++) {
        int col = h*DH + na*8 + c2;
        int qrow = q0 + wid*16 + r0;
        if (qrow < LL) {
            size_t o = (((size_t)(b*LL + qrow))*DD + col) >> 1;
            ((unsigned*)outh)[o] = packh(sO[na][0]*inv0, sO[na][1]*inv0);
        }
        if (qrow + 8 < LL) {
            size_t o = (((size_t)(b*LL + qrow + 8))*DD + col) >> 1;
            ((unsigned*)outh)[o] = packh(sO[na][2]*inv1, sO[na][3]*inv1);
        }
    }
}

// ---------------- residual add + LayerNorm (warp/row) + optional fp16 out --
__global__ void __launch_bounds__(256) add_ln_kernel(
    const float* __restrict__ x, const float* __restrict__ y,
    const float* __restrict__ gam, const float* __restrict__ bet,
    float* __restrict__ out, __half* __restrict__ oh,
    int doadd)
{
    int warp = threadIdx.x >> 5, lane = threadIdx.x & 31;
    int row = blockIdx.x*8 + warp;
    const float* xr = x + (size_t)row*DD + lane*8;
    float v[8];
    float4 va = *(const float4*)(xr);
    float4 vb = *(const float4*)(xr + 4);
    v[0]=va.x; v[1]=va.y; v[2]=va.z; v[3]=va.w;
    v[4]=vb.x; v[5]=vb.y; v[6]=vb.z; v[7]=vb.w;
    if (doadd) {
        const float* yr = y + (size_t)row*DD + lane*8;
        float4 ya = *(const float4*)(yr);
        float4 yb = *(const float4*)(yr + 4);
        v[0]+=ya.x; v[1]+=ya.y; v[2]+=ya.z; v[3]+=ya.w;
        v[4]+=yb.x; v[5]+=yb.y; v[6]+=yb.z; v[7]+=yb.w;
    }
    float s = 0.f;
    #pragma unroll
    for (int i=0;i<8;i++) s += v[i];
    #pragma unroll
    for (int off=16; off; off>>=1) s += __shfl_xor_sync(0xffffffffu, s, off);
    float mean = s * (1.f/DD);
    float s2 = 0.f;
    #pragma unroll
    for (int i=0;i<8;i++) { v[i] -= mean; s2 += v[i]*v[i]; }
    #pragma unroll
    for (int off=16; off; off>>=1) s2 += __shfl_xor_sync(0xffffffffu, s2, off);
    float rstd = rsqrtf(s2 * (1.f/DD) + 1e-5f);
    const float* gp = gam + lane*8;
    const float* bp = bet + lane*8;
    float4 ga = *(const float4*)(gp);
    float4 gb = *(const float4*)(gp+4);
    float4 ba = *(const float4*)(bp);
    float4 bb = *(const float4*)(bp+4);
    float g[8] = {ga.x,ga.y,ga.z,ga.w,gb.x,gb.y,gb.z,gb.w};
    float be[8] = {ba.x,ba.y,ba.z,ba.w,bb.x,bb.y,bb.z,bb.w};
    float o[8];
    #pragma unroll
    for (int i=0;i<8;i++) o[i] = v[i]*rstd*g[i] + be[i];
    float* op = out + (size_t)row*DD + lane*8;
    *(float4*)(op)   = make_float4(o[0],o[1],o[2],o[3]);
    *(float4*)(op+4) = make_float4(o[4],o[5],o[6],o[7]);
    if (oh) {
        unsigned hw[4];
        hw[0] = packh(o[0],o[1]);
        hw[1] = packh(o[2],o[3]);
        hw[2] = packh(o[4],o[5]);
        hw[3] = packh(o[6],o[7]);
        size_t ob = ((size_t)row*DD + lane*8) >> 1;
        *(uint4*)((unsigned*)oh + ob) = make_uint4(hw[0],hw[1],hw[2],hw[3]);
    }
}

// ---------------- launch ----------------
extern "C" void kernel_launch(void* const* d_in, const int* in_sizes, int n_in,
                              void* d_out, int out_size)
{
    const float* x_img          = (const float*)d_in[0];
    const void*  pmask          = (const void*)d_in[1];
    const int*   valid_idx      = (const int*)d_in[2];
    const float* pe_w           = (const float*)d_in[3];
    const float* pe_b           = (const float*)d_in[4];
    const float* spos           = (const float*)d_in[5];
    const float* Wqkv           = (const float*)d_in[6];
    const float* bqkv           = (const float*)d_in[7];
    const float* Wo             = (const float*)d_in[8];
    const float* bo             = (const float*)d_in[9];
    const float* ln1s           = (const float*)d_in[10];
    const float* ln1b           = (const float*)d_in[11];
    const float* W1             = (const float*)d_in[12];
    const float* b1             = (const float*)d_in[13];
    const float* W2             = (const float*)d_in[14];
    const float* b2             = (const float*)d_in[15];
    const float* ln2s           = (const float*)d_in[16];
    const float* ln2b           = (const float*)d_in[17];
    const float* nfs            = (const float*)d_in[18];
    const float* nfb            = (const float*)d_in[19];
    float* out = (float*)d_out;

    float *px, *py;
    __half *pxh, *path, *pffh, *pwh;
    cudaGetSymbolAddress((void**)&px,   g_x);
    cudaGetSymbolAddress((void**)&py,   g_y);
    cudaGetSymbolAddress((void**)&pxh,  g_xh);
    cudaGetSymbolAddress((void**)&path, g_atth);
    cudaGetSymbolAddress((void**)&pffh, g_ffh);
    cudaGetSymbolAddress((void**)&pwh,  g_wh);

    cudaFuncSetAttribute(attn_kernel, cudaFuncAttributeMaxDynamicSharedMemorySize, ATT_SMEM);
    cudaFuncSetAttribute(gemm_kernel<2,0>, cudaFuncAttributeMaxDynamicSharedMemorySize, GEMM_SMEM);
    cudaFuncSetAttribute(gemm_kernel<0,0>, cudaFuncAttributeMaxDynamicSharedMemorySize, GEMM_SMEM);
    cudaFuncSetAttribute(gemm_kernel<1,1>, cudaFuncAttributeMaxDynamicSharedMemorySize, GEMM_SMEM);

    prep_weights_kernel<<<WTOTAL/256, 256>>>(Wqkv, Wo, W1, W2);
    build_vis_kernel<<<(BB*TT+255)/256, 256>>>(pmask, valid_idx);
    embed_kernel<<<MM/16, 256>>>(x_img, valid_idx, pe_w, pe_b, spos);
    cvt_x_kernel<<<MM*DD/512, 256>>>();

    for (int i = 0; i < NLAYERS; i++) {
        const __half* wh = pwh + (size_t)i*WLAYER;
        // QKV GEMM (fp16 x) with fused Q/K/V^T epilogue
        gemm_kernel<2,0><<<dim3(MM/128, 6), 256, GEMM_SMEM>>>(
            pxh, wh + WOFS_QKV, bqkv + i*768,
            nullptr, nullptr, 768, 256);
        attn_kernel<<<dim3(17, BB*NHEAD), 256, ATT_SMEM>>>(path);
        // Wo GEMM
        gemm_kernel<0,0><<<dim3(MM/128, 2), 256, GEMM_SMEM>>>(
            path, wh + WOFS_O, bo + i*256,
            py, nullptr, 256, 256);
        add_ln_kernel<<<MM/8, 256>>>(px, py, ln1s + i*DD, ln1b + i*DD, px, pxh, 1);
        // FF1 GEMM -> relu -> fp16
        gemm_kernel<1,1><<<dim3(MM/128, 8), 256, GEMM_SMEM>>>(
            pxh, wh + WOFS_1, b1 + i*DFF,
            nullptr, pffh, 1024, 256);
        // FF2 GEMM
        gemm_kernel<0,0><<<dim3(MM/128, 2), 256, GEMM_SMEM>>>(
            pffh, wh + WOFS_2, b2 + i*256,
            py, nullptr, 256, 1024);
        add_ln_kernel<<<MM/8, 256>>>(px, py, ln2s + i*DD, ln2b + i*DD, px, pxh, 1);
    }
    add_ln_kernel<<<MM/8, 256>>>(px, px, nfs, nfb, out, nullptr, 0);
}